// round 6
// baseline (speedup 1.0000x reference)
#include <cuda_runtime.h>
#include <math.h>

#define Bq    2
#define Tq    2048
#define BT    4096
#define Dq    512
#define Sq    256
#define Lq    4
#define DFFq  1368
#define Vq    32000
#define EPSq  1e-5f
#define NCHUNK 16
#define CLEN   128   // Tq / NCHUNK

// ---------------- scratch (no cudaMalloc allowed) ----------------
__device__ __align__(128) float g_h [(size_t)BT * Dq];    // residual stream
__device__ __align__(128) float g_ln[(size_t)BT * Dq];    // LN output
__device__ __align__(128) float g_bu[(size_t)BT * Sq];    // Bu, then scanned h
__device__ __align__(128) float g_carry[Bq * Sq * NCHUNK];
__device__ __align__(128) float g_ff[(size_t)BT * DFFq];  // gate, then gated prod

// ---------------- embedding: h = emb[x] + pos[t] ----------------
__global__ void k_embed(const int* __restrict__ x, const float* __restrict__ emb,
                        const float* __restrict__ pos)
{
    const int row = blockIdx.x;          // 0..4095 = b*2048 + t
    const int t   = row & (Tq - 1);
    const int tok = x[row];
    const float4* e = (const float4*)(emb + (size_t)tok * Dq);
    const float4* p = (const float4*)(pos + (size_t)t * Dq);
    float4* o = (float4*)(g_h + (size_t)row * Dq);
    const int c = threadIdx.x;           // 128 threads, 4 floats each
    float4 a = e[c], b = p[c];
    o[c] = make_float4(a.x + b.x, a.y + b.y, a.z + b.z, a.w + b.w);
}

// ---------------- layernorm (one block per token row) ----------------
__global__ void k_ln(const float* __restrict__ in, float* __restrict__ out,
                     const float* __restrict__ w, const float* __restrict__ b)
{
    const int row = blockIdx.x;
    const int c = threadIdx.x;           // 0..127
    const float4 v = ((const float4*)(in + (size_t)row * Dq))[c];
    float s  = v.x + v.y + v.z + v.w;
    float ss = v.x*v.x + v.y*v.y + v.z*v.z + v.w*v.w;
#pragma unroll
    for (int o = 16; o > 0; o >>= 1) {
        s  += __shfl_xor_sync(0xffffffffu, s,  o);
        ss += __shfl_xor_sync(0xffffffffu, ss, o);
    }
    __shared__ float sm[10];
    const int wid = c >> 5;
    if ((c & 31) == 0) { sm[wid] = s; sm[4 + wid] = ss; }
    __syncthreads();
    if (c == 0) {
        float S1 = sm[0] + sm[1] + sm[2] + sm[3];
        float S2 = sm[4] + sm[5] + sm[6] + sm[7];
        float mu  = S1 * (1.0f / Dq);
        float var = S2 * (1.0f / Dq) - mu * mu;
        sm[8] = mu;
        sm[9] = rsqrtf(var + EPSq);
    }
    __syncthreads();
    const float mu = sm[8], rs = sm[9];
    const float4 wv = ((const float4*)w)[c];
    const float4 bv = ((const float4*)b)[c];
    float4 o;
    o.x = (v.x - mu) * rs * wv.x + bv.x;
    o.y = (v.y - mu) * rs * wv.y + bv.y;
    o.z = (v.z - mu) * rs * wv.z + bv.z;
    o.w = (v.w - mu) * rs * wv.w + bv.w;
    ((float4*)(out + (size_t)row * Dq))[c] = o;
}

// ---------------- SGEMM: C = A[M,K] * B[N,K]^T, fused epilogues ----------------
// MODE 0: C = acc
// MODE 1: C = silu(C) * acc                       (SwiGLU second GEMM)
// MODE 2: C = C + acc + aux1[n] * aux2[m,n]       (SSM residual: Dp*u)
// MODE 3: C = C + acc                             (FFN residual)
// MODE 4: C = acc + aux1[n]                       (head bias)
template<int MODE>
__global__ void __launch_bounds__(256, 2)
k_gemm(const float* __restrict__ A, const float* __restrict__ B,
       float* __restrict__ C, int M, int N, int K,
       const float* __restrict__ aux1, const float* __restrict__ aux2)
{
    __shared__ float As[8][128];
    __shared__ float Bs[8][128];
    const int bm = blockIdx.y * 128;
    const int bn = blockIdx.x * 128;
    const int tid = threadIdx.x;
    const int tx = tid & 15;
    const int ty = tid >> 4;
    const int lrow = tid >> 1;           // 0..127
    const int lcol = (tid & 1) * 4;      // 0 or 4

    float acc[8][8];
#pragma unroll
    for (int i = 0; i < 8; i++)
#pragma unroll
        for (int j = 0; j < 8; j++) acc[i][j] = 0.f;

    const float* Aptr = A + (size_t)(bm + lrow) * K + lcol;
    const float* Bptr = B + (size_t)(bn + lrow) * K + lcol;
    const bool bvalid = (bn + lrow) < N;

    for (int k0 = 0; k0 < K; k0 += 8) {
        float4 av = *(const float4*)(Aptr + k0);
        float4 bv = make_float4(0.f, 0.f, 0.f, 0.f);
        if (bvalid) bv = *(const float4*)(Bptr + k0);
        __syncthreads();
        As[lcol + 0][lrow] = av.x;
        As[lcol + 1][lrow] = av.y;
        As[lcol + 2][lrow] = av.z;
        As[lcol + 3][lrow] = av.w;
        Bs[lcol + 0][lrow] = bv.x;
        Bs[lcol + 1][lrow] = bv.y;
        Bs[lcol + 2][lrow] = bv.z;
        Bs[lcol + 3][lrow] = bv.w;
        __syncthreads();
#pragma unroll
        for (int k = 0; k < 8; k++) {
            float a[8], b[8];
            *(float4*)(a)     = *(const float4*)(&As[k][ty * 8]);
            *(float4*)(a + 4) = *(const float4*)(&As[k][ty * 8 + 4]);
            *(float4*)(b)     = *(const float4*)(&Bs[k][tx * 8]);
            *(float4*)(b + 4) = *(const float4*)(&Bs[k][tx * 8 + 4]);
#pragma unroll
            for (int i = 0; i < 8; i++)
#pragma unroll
                for (int j = 0; j < 8; j++)
                    acc[i][j] = fmaf(a[i], b[j], acc[i][j]);
        }
    }

#pragma unroll
    for (int i = 0; i < 8; i++) {
        const int m = bm + ty * 8 + i;
        const size_t rowoff = (size_t)m * N;
#pragma unroll
        for (int jj = 0; jj < 2; jj++) {
            const int n = bn + tx * 8 + jj * 4;
            if (n >= N) continue;       // N is always a multiple of 4
            float4 r;
            r.x = acc[i][jj*4+0]; r.y = acc[i][jj*4+1];
            r.z = acc[i][jj*4+2]; r.w = acc[i][jj*4+3];
            float4* cp = (float4*)(C + rowoff + n);
            if (MODE == 0) {
                *cp = r;
            } else if (MODE == 1) {
                float4 g = *cp;
                r.x *= g.x / (1.f + __expf(-g.x));
                r.y *= g.y / (1.f + __expf(-g.y));
                r.z *= g.z / (1.f + __expf(-g.z));
                r.w *= g.w / (1.f + __expf(-g.w));
                *cp = r;
            } else if (MODE == 2) {
                float4 c  = *cp;
                float4 dp = *(const float4*)(aux1 + n);
                float4 u  = *(const float4*)(aux2 + rowoff + n);
                r.x += c.x + dp.x * u.x;
                r.y += c.y + dp.y * u.y;
                r.z += c.z + dp.z * u.z;
                r.w += c.w + dp.w * u.w;
                *cp = r;
            } else if (MODE == 3) {
                float4 c = *cp;
                r.x += c.x; r.y += c.y; r.z += c.z; r.w += c.w;
                *cp = r;
            } else {
                float4 bb = *(const float4*)(aux1 + n);
                r.x += bb.x; r.y += bb.y; r.z += bb.z; r.w += bb.w;
                *cp = r;
            }
        }
    }
}

// ---------------- SSM scan: h[t] = lam*h[t-1] + Bu[t], chunked ----------------
// Phase 1: local scan per (b, s, chunk), zero initial state; record carry.
__global__ void k_scan1(const float* __restrict__ loglam)
{
    const int idx   = blockIdx.x * blockDim.x + threadIdx.x;  // 0..8191
    const int s     = idx & (Sq - 1);
    const int b     = (idx >> 8) & 1;
    const int chunk = idx >> 9;
    const float lam = 1.f / (1.f + expf(-loglam[s]));
    float* p = g_bu + ((size_t)(b * Tq + chunk * CLEN)) * Sq + s;
    float h = 0.f;
    float buf[4];
#pragma unroll
    for (int j = 0; j < 4; j++) buf[j] = p[(size_t)j * Sq];
    for (int j0 = 0; j0 < CLEN; j0 += 4) {
        float c0 = buf[0], c1 = buf[1], c2 = buf[2], c3 = buf[3];
        if (j0 + 4 < CLEN) {
#pragma unroll
            for (int j = 0; j < 4; j++) buf[j] = p[(size_t)(j0 + 4 + j) * Sq];
        }
        h = fmaf(lam, h, c0); p[(size_t)(j0 + 0) * Sq] = h;
        h = fmaf(lam, h, c1); p[(size_t)(j0 + 1) * Sq] = h;
        h = fmaf(lam, h, c2); p[(size_t)(j0 + 2) * Sq] = h;
        h = fmaf(lam, h, c3); p[(size_t)(j0 + 3) * Sq] = h;
    }
    g_carry[((size_t)b * Sq + s) * NCHUNK + chunk] = h;
}

// Phase 2: prefix over chunk carries -> incoming state H per chunk (in place).
__global__ void k_scan2(const float* __restrict__ loglam)
{
    const int idx = blockIdx.x * blockDim.x + threadIdx.x;    // 0..511
    const int s = idx & (Sq - 1);
    const int b = idx >> 8;
    const float lam = 1.f / (1.f + expf(-loglam[s]));
    float lp = lam;
#pragma unroll
    for (int i = 0; i < 7; i++) lp *= lp;                     // lam^128
    float* cb = g_carry + ((size_t)b * Sq + s) * NCHUNK;
    float H = 0.f;
#pragma unroll
    for (int c = 0; c < NCHUNK; c++) {
        float carry = cb[c];
        cb[c] = H;                                            // incoming state
        H = fmaf(lp, H, carry);
    }
}

// Phase 3: h_full[j] = h_local[j] + lam^{j+1} * H_in
__global__ void k_scan3(const float* __restrict__ loglam)
{
    const int idx   = blockIdx.x * blockDim.x + threadIdx.x;
    const int s     = idx & (Sq - 1);
    const int b     = (idx >> 8) & 1;
    const int chunk = idx >> 9;
    if (chunk == 0) return;                                   // H = 0
    const float lam = 1.f / (1.f + expf(-loglam[s]));
    const float H = g_carry[((size_t)b * Sq + s) * NCHUNK + chunk];
    float* p = g_bu + ((size_t)(b * Tq + chunk * CLEN)) * Sq + s;
    float f = lam;
    for (int j0 = 0; j0 < CLEN; j0 += 8) {
        float v[8];
#pragma unroll
        for (int u = 0; u < 8; u++) v[u] = p[(size_t)(j0 + u) * Sq];
#pragma unroll
        for (int u = 0; u < 8; u++) { v[u] += f * H; f *= lam; }
#pragma unroll
        for (int u = 0; u < 8; u++) p[(size_t)(j0 + u) * Sq] = v[u];
    }
}

// ---------------- orchestration ----------------
extern "C" void kernel_launch(void* const* d_in, const int* in_sizes, int n_in,
                              void* d_out, int out_size)
{
    const int*   x      = (const int*)  d_in[0];
    const float* emb    = (const float*)d_in[1];
    const float* pos    = (const float*)d_in[2];
    const float* loglam = (const float*)d_in[3];
    const float* Bw     = (const float*)d_in[4];
    const float* Cw     = (const float*)d_in[5];
    const float* Dp     = (const float*)d_in[6];
    const float* n1w    = (const float*)d_in[7];
    const float* n1b    = (const float*)d_in[8];
    const float* n2w    = (const float*)d_in[9];
    const float* n2b    = (const float*)d_in[10];
    const float* w1     = (const float*)d_in[11];
    const float* w2     = (const float*)d_in[12];
    const float* w3     = (const float*)d_in[13];
    const float* now    = (const float*)d_in[14];
    const float* nob    = (const float*)d_in[15];
    const float* headW  = (const float*)d_in[16];
    const float* headb  = (const float*)d_in[17];
    float* out = (float*)d_out;

    void *ph, *pl, *pb, *pf;
    cudaGetSymbolAddress(&ph, g_h);
    cudaGetSymbolAddress(&pl, g_ln);
    cudaGetSymbolAddress(&pb, g_bu);
    cudaGetSymbolAddress(&pf, g_ff);
    float* h  = (float*)ph;
    float* ln = (float*)pl;
    float* bu = (float*)pb;
    float* ff = (float*)pf;

    k_embed<<<BT, 128>>>(x, emb, pos);

    for (int l = 0; l < Lq; l++) {
        // ---- SSM block ----
        k_ln<<<BT, 128>>>(h, ln, n1w + l * Dq, n1b + l * Dq);
        k_gemm<0><<<dim3(Sq / 128, BT / 128), 256>>>(
            ln, Bw + (size_t)l * Sq * Dq, bu, BT, Sq, Dq, nullptr, nullptr);
        k_scan1<<<32, 256>>>(loglam + l * Sq);
        k_scan2<<<2, 256>>>(loglam + l * Sq);
        k_scan3<<<32, 256>>>(loglam + l * Sq);
        k_gemm<2><<<dim3(Dq / 128, BT / 128), 256>>>(
            bu, Cw + (size_t)l * Dq * Sq, h, BT, Dq, Sq, Dp + l * Dq, ln);
        // ---- SwiGLU block ----
        k_ln<<<BT, 128>>>(h, ln, n2w + l * Dq, n2b + l * Dq);
        k_gemm<0><<<dim3((DFFq + 127) / 128, BT / 128), 256>>>(
            ln, w1 + (size_t)l * DFFq * Dq, ff, BT, DFFq, Dq, nullptr, nullptr);
        k_gemm<1><<<dim3((DFFq + 127) / 128, BT / 128), 256>>>(
            ln, w2 + (size_t)l * DFFq * Dq, ff, BT, DFFq, Dq, nullptr, nullptr);
        k_gemm<3><<<dim3(Dq / 128, BT / 128), 256>>>(
            ff, w3 + (size_t)l * Dq * DFFq, h, BT, Dq, DFFq, nullptr, nullptr);
    }

    // ---- head ----
    k_ln<<<BT, 128>>>(h, ln, now, nob);
    k_gemm<4><<<dim3(Vq / 128, BT / 128), 256>>>(
        ln, headW, out, BT, Vq, Dq, headb, nullptr);
}

// round 9
// speedup vs baseline: 1.9562x; 1.9562x over previous
#include <cuda_runtime.h>
#include <math.h>
#include <stdint.h>

#define Bq    2
#define Tq    2048
#define BT    4096
#define Dq    512
#define Sq    256
#define Lq    4
#define DFFq  1368
#define Vq    32000
#define EPSq  1e-5f
#define NCHUNK 16
#define CLEN   128   // Tq / NCHUNK

// ---------------- scratch (no cudaMalloc allowed) ----------------
__device__ __align__(128) float g_h [(size_t)BT * Dq];    // residual stream
__device__ __align__(128) float g_ln[(size_t)BT * Dq];    // LN output
__device__ __align__(128) float g_bu[(size_t)BT * Sq];    // Bu, then scanned h
__device__ __align__(128) float g_carry[Bq * Sq * NCHUNK];
__device__ __align__(128) float g_ff[(size_t)BT * DFFq];  // gate, then gated prod

// ---------------- helpers ----------------
__device__ __forceinline__ float tf32_rna(float f) {
    uint32_t r;
    asm("cvt.rna.tf32.f32 %0, %1;" : "=r"(r) : "f"(f));
    return __uint_as_float(r);
}
__device__ __forceinline__ void mma_tf32(float* c, const float* a, const float* b) {
    asm volatile(
        "mma.sync.aligned.m16n8k8.row.col.f32.tf32.tf32.f32 "
        "{%0,%1,%2,%3}, {%4,%5,%6,%7}, {%8,%9}, {%0,%1,%2,%3};"
        : "+f"(c[0]), "+f"(c[1]), "+f"(c[2]), "+f"(c[3])
        : "r"(__float_as_uint(a[0])), "r"(__float_as_uint(a[1])),
          "r"(__float_as_uint(a[2])), "r"(__float_as_uint(a[3])),
          "r"(__float_as_uint(b[0])), "r"(__float_as_uint(b[1])));
}

// ---------------- embedding: h = emb[x] + pos[t] ----------------
__global__ void k_embed(const int* __restrict__ x, const float* __restrict__ emb,
                        const float* __restrict__ pos)
{
    const int row = blockIdx.x;
    const int t   = row & (Tq - 1);
    const int tok = x[row];
    const float4* e = (const float4*)(emb + (size_t)tok * Dq);
    const float4* p = (const float4*)(pos + (size_t)t * Dq);
    float4* o = (float4*)(g_h + (size_t)row * Dq);
    const int c = threadIdx.x;
    float4 a = e[c], b = p[c];
    o[c] = make_float4(a.x + b.x, a.y + b.y, a.z + b.z, a.w + b.w);
}

// ---------------- layernorm ----------------
__global__ void k_ln(const float* __restrict__ in, float* __restrict__ out,
                     const float* __restrict__ w, const float* __restrict__ b)
{
    const int row = blockIdx.x;
    const int c = threadIdx.x;
    const float4 v = ((const float4*)(in + (size_t)row * Dq))[c];
    float s  = v.x + v.y + v.z + v.w;
    float ss = v.x*v.x + v.y*v.y + v.z*v.z + v.w*v.w;
#pragma unroll
    for (int o = 16; o > 0; o >>= 1) {
        s  += __shfl_xor_sync(0xffffffffu, s,  o);
        ss += __shfl_xor_sync(0xffffffffu, ss, o);
    }
    __shared__ float sm[10];
    const int wid = c >> 5;
    if ((c & 31) == 0) { sm[wid] = s; sm[4 + wid] = ss; }
    __syncthreads();
    if (c == 0) {
        float S1 = sm[0] + sm[1] + sm[2] + sm[3];
        float S2 = sm[4] + sm[5] + sm[6] + sm[7];
        float mu  = S1 * (1.0f / Dq);
        float var = S2 * (1.0f / Dq) - mu * mu;
        sm[8] = mu;
        sm[9] = rsqrtf(var + EPSq);
    }
    __syncthreads();
    const float mu = sm[8], rs = sm[9];
    const float4 wv = ((const float4*)w)[c];
    const float4 bv = ((const float4*)b)[c];
    float4 o;
    o.x = (v.x - mu) * rs * wv.x + bv.x;
    o.y = (v.y - mu) * rs * wv.y + bv.y;
    o.z = (v.z - mu) * rs * wv.z + bv.z;
    o.w = (v.w - mu) * rs * wv.w + bv.w;
    ((float4*)(out + (size_t)row * Dq))[c] = o;
}

// =================== tf32 mma.sync GEMM: C = A[M,K]*B[N,K]^T ===================
// CTA tile 128x128, K-chunk 32, 256 threads = 8 warps (2m x 4n), warp tile 64x32.
// SMEM transposed: As[k][m], Bs[k][n], row pitch 136 floats (conflict-free).
// MODE 0: C = acc
// MODE 1: C = silu(C) * acc                 (SwiGLU second GEMM)
// MODE 2: C = C + acc + aux1[n]*aux2[m,n]   (SSM residual: Dp*u)
// MODE 3: C = C + acc                       (FFN residual)
// MODE 4: C = acc + aux1[n]                 (head bias)
#define PITCH 136
#define STG   (32 * PITCH)     // floats per stage buffer

template<int MODE>
__global__ void __launch_bounds__(256, 2)
k_mma(const float* __restrict__ A, const float* __restrict__ Bm,
      float* __restrict__ C, int M, int N, int K,
      const float* __restrict__ aux1, const float* __restrict__ aux2)
{
    extern __shared__ float smem[];
    float* AS = smem;              // [2][32][136]
    float* BS = smem + 2 * STG;    // [2][32][136]

    const int tid  = threadIdx.x;
    const int wid  = tid >> 5;
    const int lane = tid & 31;
    const int gid  = lane >> 2;    // 0..7
    const int tig  = lane & 3;     // 0..3
    const int wm   = wid & 1;      // 0..1 (64-row slabs)
    const int wn   = wid >> 1;     // 0..3 (32-col slabs)
    const int bm   = blockIdx.y * 128;
    const int bn   = blockIdx.x * 128;

    float acc[4][4][4];
#pragma unroll
    for (int i = 0; i < 4; i++)
#pragma unroll
        for (int j = 0; j < 4; j++)
#pragma unroll
            for (int q = 0; q < 4; q++) acc[i][j][q] = 0.f;

    float4 pa[4], pb[4];
    const float4 z4 = make_float4(0.f, 0.f, 0.f, 0.f);

    const int nk = (K + 31) >> 5;

    // ---- prologue: load + stage chunk 0 ----
#pragma unroll
    for (int i = 0; i < 4; i++) {
        const int idx = i * 256 + tid;
        const int r   = idx & 127;
        const int kk  = (idx >> 7) << 2;
        pa[i] = (kk < K) ? *(const float4*)(A  + (size_t)(bm + r) * K + kk) : z4;
        pb[i] = (kk < K && (bn + r) < N) ? *(const float4*)(Bm + (size_t)(bn + r) * K + kk) : z4;
    }
#pragma unroll
    for (int i = 0; i < 4; i++) {
        const int idx = i * 256 + tid;
        const int r   = idx & 127;
        const int k   = (idx >> 7) << 2;
        float* as = AS + (size_t)k * PITCH + r;
        float* bs = BS + (size_t)k * PITCH + r;
        as[0*PITCH] = tf32_rna(pa[i].x); as[1*PITCH] = tf32_rna(pa[i].y);
        as[2*PITCH] = tf32_rna(pa[i].z); as[3*PITCH] = tf32_rna(pa[i].w);
        bs[0*PITCH] = tf32_rna(pb[i].x); bs[1*PITCH] = tf32_rna(pb[i].y);
        bs[2*PITCH] = tf32_rna(pb[i].z); bs[3*PITCH] = tf32_rna(pb[i].w);
    }
    __syncthreads();

    for (int kch = 0; kch < nk; kch++) {
        // prefetch next chunk into registers
        if (kch + 1 < nk) {
            const int k0 = (kch + 1) << 5;
#pragma unroll
            for (int i = 0; i < 4; i++) {
                const int idx = i * 256 + tid;
                const int r   = idx & 127;
                const int kk  = k0 + ((idx >> 7) << 2);
                pa[i] = (kk < K) ? *(const float4*)(A  + (size_t)(bm + r) * K + kk) : z4;
                pb[i] = (kk < K && (bn + r) < N) ? *(const float4*)(Bm + (size_t)(bn + r) * K + kk) : z4;
            }
        }
        // compute on current buffer
        {
            const float* as = AS + (size_t)(kch & 1) * STG;
            const float* bs = BS + (size_t)(kch & 1) * STG;
#pragma unroll
            for (int ks = 0; ks < 4; ks++) {
                const int kb = ks * 8;
                float afr[4][4], bfr[4][2];
#pragma unroll
                for (int mi = 0; mi < 4; mi++) {
                    const int m0 = wm * 64 + mi * 16;
                    const float* r0 = as + (size_t)(kb + tig)     * PITCH + m0 + gid;
                    const float* r4 = as + (size_t)(kb + tig + 4) * PITCH + m0 + gid;
                    afr[mi][0] = r0[0];
                    afr[mi][1] = r0[8];
                    afr[mi][2] = r4[0];
                    afr[mi][3] = r4[8];
                }
#pragma unroll
                for (int ni = 0; ni < 4; ni++) {
                    const int n0 = wn * 32 + ni * 8;
                    bfr[ni][0] = bs[(size_t)(kb + tig)     * PITCH + n0 + gid];
                    bfr[ni][1] = bs[(size_t)(kb + tig + 4) * PITCH + n0 + gid];
                }
#pragma unroll
                for (int mi = 0; mi < 4; mi++)
#pragma unroll
                    for (int ni = 0; ni < 4; ni++)
                        mma_tf32(acc[mi][ni], afr[mi], bfr[ni]);
            }
        }
        // stage next chunk into the other buffer
        if (kch + 1 < nk) {
            float* AS1 = AS + (size_t)((kch + 1) & 1) * STG;
            float* BS1 = BS + (size_t)((kch + 1) & 1) * STG;
#pragma unroll
            for (int i = 0; i < 4; i++) {
                const int idx = i * 256 + tid;
                const int r   = idx & 127;
                const int k   = (idx >> 7) << 2;
                float* as = AS1 + (size_t)k * PITCH + r;
                float* bs = BS1 + (size_t)k * PITCH + r;
                as[0*PITCH] = tf32_rna(pa[i].x); as[1*PITCH] = tf32_rna(pa[i].y);
                as[2*PITCH] = tf32_rna(pa[i].z); as[3*PITCH] = tf32_rna(pa[i].w);
                bs[0*PITCH] = tf32_rna(pb[i].x); bs[1*PITCH] = tf32_rna(pb[i].y);
                bs[2*PITCH] = tf32_rna(pb[i].z); bs[3*PITCH] = tf32_rna(pb[i].w);
            }
        }
        __syncthreads();
    }

    // ---- epilogue ----
#pragma unroll
    for (int mi = 0; mi < 4; mi++) {
        const int r0 = bm + wm * 64 + mi * 16 + gid;
#pragma unroll
        for (int half = 0; half < 2; half++) {
            const int m = r0 + half * 8;
            const size_t rowoff = (size_t)m * N;
#pragma unroll
            for (int ni = 0; ni < 4; ni++) {
                const int n0 = bn + wn * 32 + ni * 8;
                if (n0 >= N) continue;            // N is a multiple of 8
                const int n = n0 + tig * 2;
                float2 rv;
                rv.x = acc[mi][ni][half * 2 + 0];
                rv.y = acc[mi][ni][half * 2 + 1];
                float2* cp = (float2*)(C + rowoff + n);
                if (MODE == 0) {
                    *cp = rv;
                } else if (MODE == 1) {
                    float2 g = *cp;
                    rv.x *= g.x / (1.f + __expf(-g.x));
                    rv.y *= g.y / (1.f + __expf(-g.y));
                    *cp = rv;
                } else if (MODE == 2) {
                    float2 c  = *cp;
                    float2 dp = *(const float2*)(aux1 + n);
                    float2 u  = *(const float2*)(aux2 + rowoff + n);
                    rv.x += c.x + dp.x * u.x;
                    rv.y += c.y + dp.y * u.y;
                    *cp = rv;
                } else if (MODE == 3) {
                    float2 c = *cp;
                    rv.x += c.x; rv.y += c.y;
                    *cp = rv;
                } else {
                    float2 bb = *(const float2*)(aux1 + n);
                    rv.x += bb.x; rv.y += bb.y;
                    *cp = rv;
                }
            }
        }
    }
}

#define SMEM_MMA (4 * STG * sizeof(float))   // 69632 bytes

// ---------------- SSM scan: h[t] = lam*h[t-1] + Bu[t], chunked ----------------
__global__ void k_scan1(const float* __restrict__ loglam)
{
    const int idx   = blockIdx.x * blockDim.x + threadIdx.x;
    const int s     = idx & (Sq - 1);
    const int b     = (idx >> 8) & 1;
    const int chunk = idx >> 9;
    const float lam = 1.f / (1.f + expf(-loglam[s]));
    float* p = g_bu + ((size_t)(b * Tq + chunk * CLEN)) * Sq + s;
    float h = 0.f;
    float buf[4];
#pragma unroll
    for (int j = 0; j < 4; j++) buf[j] = p[(size_t)j * Sq];
    for (int j0 = 0; j0 < CLEN; j0 += 4) {
        float c0 = buf[0], c1 = buf[1], c2 = buf[2], c3 = buf[3];
        if (j0 + 4 < CLEN) {
#pragma unroll
            for (int j = 0; j < 4; j++) buf[j] = p[(size_t)(j0 + 4 + j) * Sq];
        }
        h = fmaf(lam, h, c0); p[(size_t)(j0 + 0) * Sq] = h;
        h = fmaf(lam, h, c1); p[(size_t)(j0 + 1) * Sq] = h;
        h = fmaf(lam, h, c2); p[(size_t)(j0 + 2) * Sq] = h;
        h = fmaf(lam, h, c3); p[(size_t)(j0 + 3) * Sq] = h;
    }
    g_carry[((size_t)b * Sq + s) * NCHUNK + chunk] = h;
}

__global__ void k_scan2(const float* __restrict__ loglam)
{
    const int idx = blockIdx.x * blockDim.x + threadIdx.x;
    const int s = idx & (Sq - 1);
    const int b = idx >> 8;
    const float lam = 1.f / (1.f + expf(-loglam[s]));
    float lp = lam;
#pragma unroll
    for (int i = 0; i < 7; i++) lp *= lp;    // lam^128
    float* cb = g_carry + ((size_t)b * Sq + s) * NCHUNK;
    float H = 0.f;
#pragma unroll
    for (int c = 0; c < NCHUNK; c++) {
        float carry = cb[c];
        cb[c] = H;
        H = fmaf(lp, H, carry);
    }
}

__global__ void k_scan3(const float* __restrict__ loglam)
{
    const int idx   = blockIdx.x * blockDim.x + threadIdx.x;
    const int s     = idx & (Sq - 1);
    const int b     = (idx >> 8) & 1;
    const int chunk = idx >> 9;
    if (chunk == 0) return;
    const float lam = 1.f / (1.f + expf(-loglam[s]));
    const float H = g_carry[((size_t)b * Sq + s) * NCHUNK + chunk];
    float* p = g_bu + ((size_t)(b * Tq + chunk * CLEN)) * Sq + s;
    float f = lam;
    for (int j0 = 0; j0 < CLEN; j0 += 8) {
        float v[8];
#pragma unroll
        for (int u = 0; u < 8; u++) v[u] = p[(size_t)(j0 + u) * Sq];
#pragma unroll
        for (int u = 0; u < 8; u++) { v[u] += f * H; f *= lam; }
#pragma unroll
        for (int u = 0; u < 8; u++) p[(size_t)(j0 + u) * Sq] = v[u];
    }
}

// ---------------- orchestration ----------------
extern "C" void kernel_launch(void* const* d_in, const int* in_sizes, int n_in,
                              void* d_out, int out_size)
{
    const int*   x      = (const int*)  d_in[0];
    const float* emb    = (const float*)d_in[1];
    const float* pos    = (const float*)d_in[2];
    const float* loglam = (const float*)d_in[3];
    const float* Bw     = (const float*)d_in[4];
    const float* Cw     = (const float*)d_in[5];
    const float* Dp     = (const float*)d_in[6];
    const float* n1w    = (const float*)d_in[7];
    const float* n1b    = (const float*)d_in[8];
    const float* n2w    = (const float*)d_in[9];
    const float* n2b    = (const float*)d_in[10];
    const float* w1     = (const float*)d_in[11];
    const float* w2     = (const float*)d_in[12];
    const float* w3     = (const float*)d_in[13];
    const float* now    = (const float*)d_in[14];
    const float* nob    = (const float*)d_in[15];
    const float* headW  = (const float*)d_in[16];
    const float* headb  = (const float*)d_in[17];
    float* out = (float*)d_out;

    void *ph, *pl, *pb, *pf;
    cudaGetSymbolAddress(&ph, g_h);
    cudaGetSymbolAddress(&pl, g_ln);
    cudaGetSymbolAddress(&pb, g_bu);
    cudaGetSymbolAddress(&pf, g_ff);
    float* h  = (float*)ph;
    float* ln = (float*)pl;
    float* bu = (float*)pb;
    float* ff = (float*)pf;

    cudaFuncSetAttribute(k_mma<0>, cudaFuncAttributeMaxDynamicSharedMemorySize, SMEM_MMA);
    cudaFuncSetAttribute(k_mma<1>, cudaFuncAttributeMaxDynamicSharedMemorySize, SMEM_MMA);
    cudaFuncSetAttribute(k_mma<2>, cudaFuncAttributeMaxDynamicSharedMemorySize, SMEM_MMA);
    cudaFuncSetAttribute(k_mma<3>, cudaFuncAttributeMaxDynamicSharedMemorySize, SMEM_MMA);
    cudaFuncSetAttribute(k_mma<4>, cudaFuncAttributeMaxDynamicSharedMemorySize, SMEM_MMA);

    const dim3 gBu(Sq / 128, BT / 128);
    const dim3 gC (Dq / 128, BT / 128);
    const dim3 gFF((DFFq + 127) / 128, BT / 128);
    const dim3 gW3(Dq / 128, BT / 128);
    const dim3 gHd(Vq / 128, BT / 128);

    k_embed<<<BT, 128>>>(x, emb, pos);

    for (int l = 0; l < Lq; l++) {
        // ---- SSM block ----
        k_ln<<<BT, 128>>>(h, ln, n1w + l * Dq, n1b + l * Dq);
        k_mma<0><<<gBu, 256, SMEM_MMA>>>(ln, Bw + (size_t)l * Sq * Dq, bu, BT, Sq, Dq, nullptr, nullptr);
        k_scan1<<<32, 256>>>(loglam + l * Sq);
        k_scan2<<<2, 256>>>(loglam + l * Sq);
        k_scan3<<<32, 256>>>(loglam + l * Sq);
        k_mma<2><<<gC, 256, SMEM_MMA>>>(bu, Cw + (size_t)l * Dq * Sq, h, BT, Dq, Sq, Dp + l * Dq, ln);
        // ---- SwiGLU block ----
        k_ln<<<BT, 128>>>(h, ln, n2w + l * Dq, n2b + l * Dq);
        k_mma<0><<<gFF, 256, SMEM_MMA>>>(ln, w1 + (size_t)l * DFFq * Dq, ff, BT, DFFq, Dq, nullptr, nullptr);
        k_mma<1><<<gFF, 256, SMEM_MMA>>>(ln, w2 + (size_t)l * DFFq * Dq, ff, BT, DFFq, Dq, nullptr, nullptr);
        k_mma<3><<<gW3, 256, SMEM_MMA>>>(ff, w3 + (size_t)l * Dq * DFFq, h, BT, Dq, DFFq, nullptr, nullptr);
    }

    // ---- head ----
    k_ln<<<BT, 128>>>(h, ln, now, nob);
    k_mma<4><<<gHd, 256, SMEM_MMA>>>(ln, headW, out, BT, Vq, Dq, headb, nullptr);
}

// round 10
// speedup vs baseline: 2.5887x; 1.3233x over previous
#include <cuda_runtime.h>
#include <cuda_fp16.h>
#include <math.h>
#include <stdint.h>

#define Bq    2
#define Tq    2048
#define BT    4096
#define Dq    512
#define Sq    256
#define Lq    4
#define DFFq  1368
#define Vq    32000
#define EPSq  1e-5f
#define NCHUNK 16
#define CLEN   128   // Tq / NCHUNK

// ---------------- scratch (no cudaMalloc allowed) ----------------
__device__ __align__(128) float g_h [(size_t)BT * Dq];    // residual stream
__device__ __align__(128) float g_ln[(size_t)BT * Dq];    // LN output
__device__ __align__(128) float g_bu[(size_t)BT * Sq];    // Bu, then scanned h
__device__ __align__(128) float g_carry[Bq * Sq * NCHUNK];
__device__ __align__(128) float g_ff[(size_t)BT * DFFq];  // gate, then gated prod

// ---------------- helpers ----------------
__device__ __forceinline__ uint32_t pack_h2(float x, float y) {
    half2 h = __floats2half2_rn(x, y);
    return *(uint32_t*)&h;
}
__device__ __forceinline__ void ldm_x4(uint32_t* r, uint32_t addr) {
    asm volatile("ldmatrix.sync.aligned.m8n8.x4.shared.b16 {%0,%1,%2,%3}, [%4];"
                 : "=r"(r[0]), "=r"(r[1]), "=r"(r[2]), "=r"(r[3]) : "r"(addr));
}
__device__ __forceinline__ void mma_f16(float* c, const uint32_t* a, uint32_t b0, uint32_t b1) {
    asm volatile(
        "mma.sync.aligned.m16n8k16.row.col.f32.f16.f16.f32 "
        "{%0,%1,%2,%3}, {%4,%5,%6,%7}, {%8,%9}, {%0,%1,%2,%3};"
        : "+f"(c[0]), "+f"(c[1]), "+f"(c[2]), "+f"(c[3])
        : "r"(a[0]), "r"(a[1]), "r"(a[2]), "r"(a[3]), "r"(b0), "r"(b1));
}

// ---------------- embedding: h = emb[x] + pos[t] ----------------
__global__ void k_embed(const int* __restrict__ x, const float* __restrict__ emb,
                        const float* __restrict__ pos)
{
    const int row = blockIdx.x;
    const int t   = row & (Tq - 1);
    const int tok = x[row];
    const float4* e = (const float4*)(emb + (size_t)tok * Dq);
    const float4* p = (const float4*)(pos + (size_t)t * Dq);
    float4* o = (float4*)(g_h + (size_t)row * Dq);
    const int c = threadIdx.x;
    float4 a = e[c], b = p[c];
    o[c] = make_float4(a.x + b.x, a.y + b.y, a.z + b.z, a.w + b.w);
}

// ---------------- layernorm ----------------
__global__ void k_ln(const float* __restrict__ in, float* __restrict__ out,
                     const float* __restrict__ w, const float* __restrict__ b)
{
    const int row = blockIdx.x;
    const int c = threadIdx.x;
    const float4 v = ((const float4*)(in + (size_t)row * Dq))[c];
    float s  = v.x + v.y + v.z + v.w;
    float ss = v.x*v.x + v.y*v.y + v.z*v.z + v.w*v.w;
#pragma unroll
    for (int o = 16; o > 0; o >>= 1) {
        s  += __shfl_xor_sync(0xffffffffu, s,  o);
        ss += __shfl_xor_sync(0xffffffffu, ss, o);
    }
    __shared__ float sm[10];
    const int wid = c >> 5;
    if ((c & 31) == 0) { sm[wid] = s; sm[4 + wid] = ss; }
    __syncthreads();
    if (c == 0) {
        float S1 = sm[0] + sm[1] + sm[2] + sm[3];
        float S2 = sm[4] + sm[5] + sm[6] + sm[7];
        float mu  = S1 * (1.0f / Dq);
        float var = S2 * (1.0f / Dq) - mu * mu;
        sm[8] = mu;
        sm[9] = rsqrtf(var + EPSq);
    }
    __syncthreads();
    const float mu = sm[8], rs = sm[9];
    const float4 wv = ((const float4*)w)[c];
    const float4 bv = ((const float4*)b)[c];
    float4 o;
    o.x = (v.x - mu) * rs * wv.x + bv.x;
    o.y = (v.y - mu) * rs * wv.y + bv.y;
    o.z = (v.z - mu) * rs * wv.z + bv.z;
    o.w = (v.w - mu) * rs * wv.w + bv.w;
    ((float4*)(out + (size_t)row * Dq))[c] = o;
}

// =================== fp16 mma.sync GEMM: C = A[M,K]*B[N,K]^T ===================
// CTA tile 128x128, K-chunk 32, 256 threads = 8 warps (2m x 4n), warp tile 64x32.
// SMEM halfs, row-major [row][k], pitch 40 halfs (80B) -> conflict-free ldmatrix.
// blockIdx.x = m-tile (so concurrent CTAs share the B/weight tile in L2).
// MODE 0: C = acc
// MODE 1: C = silu(C) * acc                 (SwiGLU second GEMM)
// MODE 2: C = C + acc + aux1[n]*aux2[m,n]   (SSM residual: Dp*u)
// MODE 3: C = C + acc                       (FFN residual)
// MODE 4: C = acc + aux1[n]                 (head bias)
#define PITCHB 80           // bytes per row (40 halfs)
#define STGB   10240u       // bytes per stage buffer (128 rows * 80B)
#define BSOFF  20480u       // B stages start after 2 A stages
#define SMEM_MMA 40960

template<int MODE>
__global__ void __launch_bounds__(256, 2)
k_mma(const float* __restrict__ A, const float* __restrict__ Bm,
      float* __restrict__ C, int M, int N, int K,
      const float* __restrict__ aux1, const float* __restrict__ aux2)
{
    extern __shared__ char smem[];
    const uint32_t sb = (uint32_t)__cvta_generic_to_shared(smem);

    const int tid  = threadIdx.x;
    const int wid  = tid >> 5;
    const int lane = tid & 31;
    const int gid  = lane >> 2;      // 0..7
    const int tig  = lane & 3;       // 0..3
    const int wm   = wid & 1;        // 0..1 (64-row slabs)
    const int wn   = wid >> 1;       // 0..3 (32-col slabs)
    const int bm   = blockIdx.x * 128;
    const int bn   = blockIdx.y * 128;

    // ldmatrix per-lane addressing: rows lane&15, k-offset 8 for lanes>=16
    const int lrow = lane & 15;
    const int lkof = (lane >> 4) * 16;   // byte offset (8 halfs)

    float acc[4][4][4];
#pragma unroll
    for (int i = 0; i < 4; i++)
#pragma unroll
        for (int j = 0; j < 4; j++)
#pragma unroll
            for (int q = 0; q < 4; q++) acc[i][j][q] = 0.f;

    float4 pa[4], pb[4];
    const float4 z4 = make_float4(0.f, 0.f, 0.f, 0.f);
    const int nk = (K + 31) >> 5;

    // staging index: idx = i*256+tid; row = idx&127; kq = idx>>7 (0..7), k = kq*4
    const int srow = tid & 127;
    const int skq  = tid >> 7;           // 0..1; i adds 2 per step

    // ---- prologue: load + stage chunk 0 ----
#pragma unroll
    for (int i = 0; i < 4; i++) {
        const int kq = skq + i * 2;
        const int kk = kq * 4;
        pa[i] = (kk < K) ? *(const float4*)(A  + (size_t)(bm + srow) * K + kk) : z4;
        pb[i] = (kk < K && (bn + srow) < N) ? *(const float4*)(Bm + (size_t)(bn + srow) * K + kk) : z4;
    }
#pragma unroll
    for (int i = 0; i < 4; i++) {
        const int kq = skq + i * 2;
        const uint32_t off = (uint32_t)(srow * PITCHB + kq * 8);
        *(uint2*)(smem + off)         = make_uint2(pack_h2(pa[i].x, pa[i].y), pack_h2(pa[i].z, pa[i].w));
        *(uint2*)(smem + BSOFF + off) = make_uint2(pack_h2(pb[i].x, pb[i].y), pack_h2(pb[i].z, pb[i].w));
    }
    __syncthreads();

    for (int kch = 0; kch < nk; kch++) {
        // prefetch next chunk into registers
        if (kch + 1 < nk) {
            const int k0 = (kch + 1) << 5;
#pragma unroll
            for (int i = 0; i < 4; i++) {
                const int kk = k0 + (skq + i * 2) * 4;
                pa[i] = (kk < K) ? *(const float4*)(A  + (size_t)(bm + srow) * K + kk) : z4;
                pb[i] = (kk < K && (bn + srow) < N) ? *(const float4*)(Bm + (size_t)(bn + srow) * K + kk) : z4;
            }
        }
        // compute on current buffer
        {
            const uint32_t st = (uint32_t)(kch & 1) * STGB;
            const uint32_t abase = sb + st + (uint32_t)((wm * 64 + lrow) * PITCHB) + (uint32_t)lkof;
            const uint32_t bbase = sb + BSOFF + st + (uint32_t)((wn * 32 + lrow) * PITCHB) + (uint32_t)lkof;
#pragma unroll
            for (int ks = 0; ks < 2; ks++) {
                const uint32_t kb = ks * 32;   // 16 halfs = 32 bytes
                uint32_t afr[4][4];
#pragma unroll
                for (int mi = 0; mi < 4; mi++)
                    ldm_x4(afr[mi], abase + kb + (uint32_t)(mi * 16 * PITCHB));
                uint32_t bfr[2][4];
#pragma unroll
                for (int nj = 0; nj < 2; nj++)
                    ldm_x4(bfr[nj], bbase + kb + (uint32_t)(nj * 16 * PITCHB));
                // bfr[nj]: r0 = frag(2nj).b0, r1 = frag(2nj+1).b0, r2 = frag(2nj).b1, r3 = frag(2nj+1).b1
#pragma unroll
                for (int mi = 0; mi < 4; mi++)
#pragma unroll
                    for (int ni = 0; ni < 4; ni++) {
                        const int nj = ni >> 1, hi = ni & 1;
                        mma_f16(acc[mi][ni], afr[mi], bfr[nj][hi], bfr[nj][hi + 2]);
                    }
            }
        }
        // stage next chunk into the other buffer
        if (kch + 1 < nk) {
            const uint32_t st = (uint32_t)((kch + 1) & 1) * STGB;
#pragma unroll
            for (int i = 0; i < 4; i++) {
                const int kq = skq + i * 2;
                const uint32_t off = st + (uint32_t)(srow * PITCHB + kq * 8);
                *(uint2*)(smem + off)         = make_uint2(pack_h2(pa[i].x, pa[i].y), pack_h2(pa[i].z, pa[i].w));
                *(uint2*)(smem + BSOFF + off) = make_uint2(pack_h2(pb[i].x, pb[i].y), pack_h2(pb[i].z, pb[i].w));
            }
        }
        __syncthreads();
    }

    // ---- epilogue (C frag: c0,c1 -> row gid, cols 2tig..; c2,c3 -> row gid+8) ----
#pragma unroll
    for (int mi = 0; mi < 4; mi++) {
        const int r0 = bm + wm * 64 + mi * 16 + gid;
#pragma unroll
        for (int half = 0; half < 2; half++) {
            const int m = r0 + half * 8;
            const size_t rowoff = (size_t)m * N;
#pragma unroll
            for (int ni = 0; ni < 4; ni++) {
                const int n0 = bn + wn * 32 + ni * 8;
                if (n0 >= N) continue;            // N is a multiple of 8
                const int n = n0 + tig * 2;
                float2 rv;
                rv.x = acc[mi][ni][half * 2 + 0];
                rv.y = acc[mi][ni][half * 2 + 1];
                float2* cp = (float2*)(C + rowoff + n);
                if (MODE == 0) {
                    *cp = rv;
                } else if (MODE == 1) {
                    float2 g = *cp;
                    rv.x *= g.x / (1.f + __expf(-g.x));
                    rv.y *= g.y / (1.f + __expf(-g.y));
                    *cp = rv;
                } else if (MODE == 2) {
                    float2 c  = *cp;
                    float2 dp = *(const float2*)(aux1 + n);
                    float2 u  = *(const float2*)(aux2 + rowoff + n);
                    rv.x += c.x + dp.x * u.x;
                    rv.y += c.y + dp.y * u.y;
                    *cp = rv;
                } else if (MODE == 3) {
                    float2 c = *cp;
                    rv.x += c.x; rv.y += c.y;
                    *cp = rv;
                } else {
                    float2 bb = *(const float2*)(aux1 + n);
                    rv.x += bb.x; rv.y += bb.y;
                    *cp = rv;
                }
            }
        }
    }
}

// ---------------- SSM scan: h[t] = lam*h[t-1] + Bu[t], chunked ----------------
__global__ void k_scan1(const float* __restrict__ loglam)
{
    const int idx   = blockIdx.x * blockDim.x + threadIdx.x;
    const int s     = idx & (Sq - 1);
    const int b     = (idx >> 8) & 1;
    const int chunk = idx >> 9;
    const float lam = 1.f / (1.f + expf(-loglam[s]));
    float* p = g_bu + ((size_t)(b * Tq + chunk * CLEN)) * Sq + s;
    float h = 0.f;
    float buf[4];
#pragma unroll
    for (int j = 0; j < 4; j++) buf[j] = p[(size_t)j * Sq];
    for (int j0 = 0; j0 < CLEN; j0 += 4) {
        float c0 = buf[0], c1 = buf[1], c2 = buf[2], c3 = buf[3];
        if (j0 + 4 < CLEN) {
#pragma unroll
            for (int j = 0; j < 4; j++) buf[j] = p[(size_t)(j0 + 4 + j) * Sq];
        }
        h = fmaf(lam, h, c0); p[(size_t)(j0 + 0) * Sq] = h;
        h = fmaf(lam, h, c1); p[(size_t)(j0 + 1) * Sq] = h;
        h = fmaf(lam, h, c2); p[(size_t)(j0 + 2) * Sq] = h;
        h = fmaf(lam, h, c3); p[(size_t)(j0 + 3) * Sq] = h;
    }
    g_carry[((size_t)b * Sq + s) * NCHUNK + chunk] = h;
}

__global__ void k_scan2(const float* __restrict__ loglam)
{
    const int idx = blockIdx.x * blockDim.x + threadIdx.x;
    const int s = idx & (Sq - 1);
    const int b = idx >> 8;
    const float lam = 1.f / (1.f + expf(-loglam[s]));
    float lp = lam;
#pragma unroll
    for (int i = 0; i < 7; i++) lp *= lp;    // lam^128
    float* cb = g_carry + ((size_t)b * Sq + s) * NCHUNK;
    float H = 0.f;
#pragma unroll
    for (int c = 0; c < NCHUNK; c++) {
        float carry = cb[c];
        cb[c] = H;
        H = fmaf(lp, H, carry);
    }
}

__global__ void k_scan3(const float* __restrict__ loglam)
{
    const int idx   = blockIdx.x * blockDim.x + threadIdx.x;
    const int s     = idx & (Sq - 1);
    const int b     = (idx >> 8) & 1;
    const int chunk = idx >> 9;
    if (chunk == 0) return;
    const float lam = 1.f / (1.f + expf(-loglam[s]));
    const float H = g_carry[((size_t)b * Sq + s) * NCHUNK + chunk];
    float* p = g_bu + ((size_t)(b * Tq + chunk * CLEN)) * Sq + s;
    float f = lam;
    for (int j0 = 0; j0 < CLEN; j0 += 8) {
        float v[8];
#pragma unroll
        for (int u = 0; u < 8; u++) v[u] = p[(size_t)(j0 + u) * Sq];
#pragma unroll
        for (int u = 0; u < 8; u++) { v[u] += f * H; f *= lam; }
#pragma unroll
        for (int u = 0; u < 8; u++) p[(size_t)(j0 + u) * Sq] = v[u];
    }
}

// ---------------- orchestration ----------------
extern "C" void kernel_launch(void* const* d_in, const int* in_sizes, int n_in,
                              void* d_out, int out_size)
{
    const int*   x      = (const int*)  d_in[0];
    const float* emb    = (const float*)d_in[1];
    const float* pos    = (const float*)d_in[2];
    const float* loglam = (const float*)d_in[3];
    const float* Bw     = (const float*)d_in[4];
    const float* Cw     = (const float*)d_in[5];
    const float* Dp     = (const float*)d_in[6];
    const float* n1w    = (const float*)d_in[7];
    const float* n1b    = (const float*)d_in[8];
    const float* n2w    = (const float*)d_in[9];
    const float* n2b    = (const float*)d_in[10];
    const float* w1     = (const float*)d_in[11];
    const float* w2     = (const float*)d_in[12];
    const float* w3     = (const float*)d_in[13];
    const float* now    = (const float*)d_in[14];
    const float* nob    = (const float*)d_in[15];
    const float* headW  = (const float*)d_in[16];
    const float* headb  = (const float*)d_in[17];
    float* out = (float*)d_out;

    void *ph, *pl, *pb, *pf;
    cudaGetSymbolAddress(&ph, g_h);
    cudaGetSymbolAddress(&pl, g_ln);
    cudaGetSymbolAddress(&pb, g_bu);
    cudaGetSymbolAddress(&pf, g_ff);
    float* h  = (float*)ph;
    float* ln = (float*)pl;
    float* bu = (float*)pb;
    float* ff = (float*)pf;

    // grids: x = m-tiles (32), y = n-tiles  (keeps weight tiles shared in-wave)
    const dim3 gBu(BT / 128, Sq / 128);
    const dim3 gC (BT / 128, Dq / 128);
    const dim3 gFF(BT / 128, (DFFq + 127) / 128);
    const dim3 gW3(BT / 128, Dq / 128);
    const dim3 gHd(BT / 128, Vq / 128);

    k_embed<<<BT, 128>>>(x, emb, pos);

    for (int l = 0; l < Lq; l++) {
        // ---- SSM block ----
        k_ln<<<BT, 128>>>(h, ln, n1w + l * Dq, n1b + l * Dq);
        k_mma<0><<<gBu, 256, SMEM_MMA>>>(ln, Bw + (size_t)l * Sq * Dq, bu, BT, Sq, Dq, nullptr, nullptr);
        k_scan1<<<32, 256>>>(loglam + l * Sq);
        k_scan2<<<2, 256>>>(loglam + l * Sq);
        k_scan3<<<32, 256>>>(loglam + l * Sq);
        k_mma<2><<<gC, 256, SMEM_MMA>>>(bu, Cw + (size_t)l * Dq * Sq, h, BT, Dq, Sq, Dp + l * Dq, ln);
        // ---- SwiGLU block ----
        k_ln<<<BT, 128>>>(h, ln, n2w + l * Dq, n2b + l * Dq);
        k_mma<0><<<gFF, 256, SMEM_MMA>>>(ln, w1 + (size_t)l * DFFq * Dq, ff, BT, DFFq, Dq, nullptr, nullptr);
        k_mma<1><<<gFF, 256, SMEM_MMA>>>(ln, w2 + (size_t)l * DFFq * Dq, ff, BT, DFFq, Dq, nullptr, nullptr);
        k_mma<3><<<gW3, 256, SMEM_MMA>>>(ff, w3 + (size_t)l * Dq * DFFq, h, BT, Dq, DFFq, nullptr, nullptr);
    }

    // ---- head ----
    k_ln<<<BT, 128>>>(h, ln, now, nob);
    k_mma<4><<<gHd, 256, SMEM_MMA>>>(ln, headW, out, BT, Vq, Dq, headb, nullptr);
}

// round 11
// speedup vs baseline: 6.3496x; 2.4528x over previous
#include <cuda_runtime.h>
#include <cuda_fp16.h>
#include <math.h>
#include <stdint.h>

#define Bq    2
#define Tq    2048
#define BT    4096
#define Dq    512
#define Sq    256
#define Lq    4
#define DFFq  1368
#define Vq    32000
#define EPSq  1e-5f
#define NCHUNK 64
#define CLEN   32    // Tq / NCHUNK

// ---------------- fp32 scratch ----------------
__device__ __align__(128) float g_h [(size_t)BT * Dq];    // residual stream
__device__ __align__(128) float g_bu[(size_t)BT * Sq];    // Bu (fp32, scan in place)
__device__ __align__(128) float g_carry[Bq * Sq * NCHUNK];
__device__ __align__(128) float g_ff[(size_t)BT * DFFq];  // gate (fp32)

// ---------------- fp16 scratch ----------------
__device__ __align__(128) __half g_lnh[(size_t)BT * Dq];   // LN output (A operand)
__device__ __align__(128) __half g_buh[(size_t)BT * Sq];   // scanned h (A operand)
__device__ __align__(128) __half g_ffh[(size_t)BT * DFFq]; // gated product (A operand)

// ---------------- fp16 weight arena ----------------
#define CNT_HEAD (Vq * Dq)                 // 16384000
#define CNT_BW   (Lq * Sq * Dq)            // 524288
#define CNT_W    (Lq * DFFq * Dq)          // 2801664
#define OFF_HEAD 0
#define OFF_BW   (OFF_HEAD + CNT_HEAD)
#define OFF_CW   (OFF_BW + CNT_BW)
#define OFF_W1   (OFF_CW + CNT_BW)
#define OFF_W2   (OFF_W1 + CNT_W)
#define OFF_W3   (OFF_W2 + CNT_W)
#define GW_TOTAL (OFF_W3 + CNT_W)          // 25,837,568 halfs ~ 51.7 MB
__device__ __align__(128) __half g_w[(size_t)GW_TOTAL];

// ---------------- helpers ----------------
__device__ __forceinline__ uint32_t pack_h2(float x, float y) {
    __half2 h = __floats2half2_rn(x, y);
    return *(uint32_t*)&h;
}
__device__ __forceinline__ void ldm_x4(uint32_t* r, uint32_t addr) {
    asm volatile("ldmatrix.sync.aligned.m8n8.x4.shared.b16 {%0,%1,%2,%3}, [%4];"
                 : "=r"(r[0]), "=r"(r[1]), "=r"(r[2]), "=r"(r[3]) : "r"(addr));
}
__device__ __forceinline__ void mma_f16(float* c, const uint32_t* a, uint32_t b0, uint32_t b1) {
    asm volatile(
        "mma.sync.aligned.m16n8k16.row.col.f32.f16.f16.f32 "
        "{%0,%1,%2,%3}, {%4,%5,%6,%7}, {%8,%9}, {%0,%1,%2,%3};"
        : "+f"(c[0]), "+f"(c[1]), "+f"(c[2]), "+f"(c[3])
        : "r"(a[0]), "r"(a[1]), "r"(a[2]), "r"(a[3]), "r"(b0), "r"(b1));
}
__device__ __forceinline__ void cp16(uint32_t dst, const void* src, int sz) {
    asm volatile("cp.async.cg.shared.global [%0], [%1], 16, %2;"
                 :: "r"(dst), "l"(src), "r"(sz) : "memory");
}
#define CP_COMMIT() asm volatile("cp.async.commit_group;" ::: "memory")
#define CP_WAIT1()  asm volatile("cp.async.wait_group 1;" ::: "memory")
#define CP_WAIT0()  asm volatile("cp.async.wait_group 0;" ::: "memory")

// ---------------- weight convert (fp32 -> fp16), n8 = count/8 ----------------
__global__ void k_cvt(const float* __restrict__ s, __half* __restrict__ d, int n8)
{
    const int i = blockIdx.x * blockDim.x + threadIdx.x;
    if (i >= n8) return;
    float4 a = ((const float4*)s)[2 * i];
    float4 b = ((const float4*)s)[2 * i + 1];
    uint4 o;
    o.x = pack_h2(a.x, a.y); o.y = pack_h2(a.z, a.w);
    o.z = pack_h2(b.x, b.y); o.w = pack_h2(b.z, b.w);
    ((uint4*)d)[i] = o;
}

// ---------------- embedding: h = emb[x] + pos[t] ----------------
__global__ void k_embed(const int* __restrict__ x, const float* __restrict__ emb,
                        const float* __restrict__ pos)
{
    const int row = blockIdx.x;
    const int t   = row & (Tq - 1);
    const int tok = x[row];
    const float4* e = (const float4*)(emb + (size_t)tok * Dq);
    const float4* p = (const float4*)(pos + (size_t)t * Dq);
    float4* o = (float4*)(g_h + (size_t)row * Dq);
    const int c = threadIdx.x;
    float4 a = e[c], b = p[c];
    o[c] = make_float4(a.x + b.x, a.y + b.y, a.z + b.z, a.w + b.w);
}

// ---------------- layernorm: fp32 in -> fp16 out ----------------
__global__ void k_ln(const float* __restrict__ in, __half* __restrict__ out,
                     const float* __restrict__ w, const float* __restrict__ b)
{
    const int row = blockIdx.x;
    const int c = threadIdx.x;
    const float4 v = ((const float4*)(in + (size_t)row * Dq))[c];
    float s  = v.x + v.y + v.z + v.w;
    float ss = v.x*v.x + v.y*v.y + v.z*v.z + v.w*v.w;
#pragma unroll
    for (int o = 16; o > 0; o >>= 1) {
        s  += __shfl_xor_sync(0xffffffffu, s,  o);
        ss += __shfl_xor_sync(0xffffffffu, ss, o);
    }
    __shared__ float sm[10];
    const int wid = c >> 5;
    if ((c & 31) == 0) { sm[wid] = s; sm[4 + wid] = ss; }
    __syncthreads();
    if (c == 0) {
        float S1 = sm[0] + sm[1] + sm[2] + sm[3];
        float S2 = sm[4] + sm[5] + sm[6] + sm[7];
        float mu  = S1 * (1.0f / Dq);
        float var = S2 * (1.0f / Dq) - mu * mu;
        sm[8] = mu;
        sm[9] = rsqrtf(var + EPSq);
    }
    __syncthreads();
    const float mu = sm[8], rs = sm[9];
    const float4 wv = ((const float4*)w)[c];
    const float4 bv = ((const float4*)b)[c];
    uint2 o;
    o.x = pack_h2((v.x - mu) * rs * wv.x + bv.x, (v.y - mu) * rs * wv.y + bv.y);
    o.y = pack_h2((v.z - mu) * rs * wv.z + bv.z, (v.w - mu) * rs * wv.w + bv.w);
    ((uint2*)(out + (size_t)row * Dq))[c] = o;
}

// =================== fp16 mma GEMM: C = A[M,K]*B[N,K]^T (half inputs) ===========
// CTA 128x128, BK=64, 3-stage cp.async pipeline, 256 thr = 8 warps (2m x 4n).
// SMEM: per stage per operand 128 rows x 128B, XOR-16B swizzle.
// MODE 0: C = acc                            (fp32 out)
// MODE 1: Ch = silu(C) * acc                 (half out; C = fp32 gate)
// MODE 2: C = C + acc + aux1[n]*aux2h[m,n]   (SSM residual)
// MODE 3: C = C + acc                        (FFN residual)
// MODE 4: C = acc + aux1[n]                  (head bias)
#define STGB 16384u
#define BOFF 49152u              // B stages after 3 A stages
#define SMEM_MMA 98304

template<int MODE>
__global__ void __launch_bounds__(256, 2)
k_mma(const __half* __restrict__ A, const __half* __restrict__ Bm,
      float* __restrict__ C, __half* __restrict__ Ch, int M, int N, int K,
      const float* __restrict__ aux1, const __half* __restrict__ aux2)
{
    extern __shared__ char smem[];
    const uint32_t sb = (uint32_t)__cvta_generic_to_shared(smem);

    const int tid  = threadIdx.x;
    const int wid  = tid >> 5;
    const int lane = tid & 31;
    const int gid  = lane >> 2;
    const int tig  = lane & 3;
    const int hi   = lane >> 4;       // 0/1: k half for ldmatrix
    const int lrow = lane & 15;
    const int rswz = lrow & 7;
    const int wm   = wid & 1;
    const int wn   = wid >> 1;
    const int bm   = blockIdx.x * 128;
    const int bn   = blockIdx.y * 128;

    // cp.async per-thread mapping: chunk = i*256+tid; row = i*32 + r0; col16 = c16
    const int r0  = tid >> 3;         // 0..31
    const int c16 = tid & 7;          // 0..7
    const uint32_t swz16 = (uint32_t)((c16 ^ (r0 & 7)) * 16);
    const __half* Asrc = A  + (size_t)(bm + r0) * K + c16 * 8;
    const __half* Bsrc = Bm + (size_t)(bn + r0) * K + c16 * 8;

    float acc[4][4][4];
#pragma unroll
    for (int i = 0; i < 4; i++)
#pragma unroll
        for (int j = 0; j < 4; j++)
#pragma unroll
            for (int q = 0; q < 4; q++) acc[i][j][q] = 0.f;

    const int nk = (K + 63) >> 6;

    // stage issuer (stage slot st = kc % 3, k0 = kc*64)
    auto issue = [&](int kc) {
        const uint32_t st = (uint32_t)(kc % 3) * STGB;
        const int k0 = kc << 6;
        const int ksz = (k0 + c16 * 8 + 8 <= K) ? 16 : 0;
#pragma unroll
        for (int i = 0; i < 4; i++) {
            const uint32_t dof = st + (uint32_t)((i * 32 + r0) * 128) + swz16;
            cp16(sb + dof, Asrc + (size_t)(i * 32) * K + k0, ksz);
            const int bsz = ((bn + i * 32 + r0) < N) ? ksz : 0;
            cp16(sb + BOFF + dof, Bsrc + (size_t)(i * 32) * K + k0, bsz);
        }
        CP_COMMIT();
    };

    issue(0);
    issue(1);

    for (int kch = 0; kch < nk; kch++) {
        CP_WAIT1();
        __syncthreads();
        if (kch + 2 < nk) issue(kch + 2);

        const uint32_t st = (uint32_t)(kch % 3) * STGB;
        const uint32_t arow = sb + st + (uint32_t)((wm * 64 + lrow) * 128);
        const uint32_t brow = sb + BOFF + st + (uint32_t)((wn * 32 + lrow) * 128);
#pragma unroll
        for (int ks = 0; ks < 4; ks++) {
            const uint32_t csw = (uint32_t)(((ks * 2 + hi) ^ rswz) * 16);
            uint32_t afr[4][4];
#pragma unroll
            for (int mi = 0; mi < 4; mi++)
                ldm_x4(afr[mi], arow + (uint32_t)(mi * 16 * 128) + csw);
            uint32_t bfr[2][4];
#pragma unroll
            for (int nj = 0; nj < 2; nj++)
                ldm_x4(bfr[nj], brow + (uint32_t)(nj * 16 * 128) + csw);
#pragma unroll
            for (int mi = 0; mi < 4; mi++)
#pragma unroll
                for (int ni = 0; ni < 4; ni++) {
                    const int nj = ni >> 1, h = ni & 1;
                    mma_f16(acc[mi][ni], afr[mi], bfr[nj][h], bfr[nj][h + 2]);
                }
        }
        __syncthreads();
    }
    CP_WAIT0();

    // ---- epilogue ----
#pragma unroll
    for (int mi = 0; mi < 4; mi++) {
        const int r0m = bm + wm * 64 + mi * 16 + gid;
#pragma unroll
        for (int half = 0; half < 2; half++) {
            const int m = r0m + half * 8;
            const size_t rowoff = (size_t)m * N;
#pragma unroll
            for (int ni = 0; ni < 4; ni++) {
                const int n0 = bn + wn * 32 + ni * 8;
                if (n0 >= N) continue;
                const int n = n0 + tig * 2;
                float2 rv;
                rv.x = acc[mi][ni][half * 2 + 0];
                rv.y = acc[mi][ni][half * 2 + 1];
                if (MODE == 0) {
                    *(float2*)(C + rowoff + n) = rv;
                } else if (MODE == 1) {
                    float2 g = *(const float2*)(C + rowoff + n);
                    rv.x *= g.x / (1.f + __expf(-g.x));
                    rv.y *= g.y / (1.f + __expf(-g.y));
                    *(__half2*)(Ch + rowoff + n) = __floats2half2_rn(rv.x, rv.y);
                } else if (MODE == 2) {
                    float2* cp = (float2*)(C + rowoff + n);
                    float2 c  = *cp;
                    float2 dp = *(const float2*)(aux1 + n);
                    float2 u  = __half22float2(*(const __half2*)(aux2 + rowoff + n));
                    rv.x += c.x + dp.x * u.x;
                    rv.y += c.y + dp.y * u.y;
                    *cp = rv;
                } else if (MODE == 3) {
                    float2* cp = (float2*)(C + rowoff + n);
                    float2 c = *cp;
                    rv.x += c.x; rv.y += c.y;
                    *cp = rv;
                } else {
                    float2 bb = *(const float2*)(aux1 + n);
                    rv.x += bb.x; rv.y += bb.y;
                    *(float2*)(C + rowoff + n) = rv;
                }
            }
        }
    }
}

// ---------------- SSM scan: h[t] = lam*h[t-1] + Bu[t], 64 chunks of 32 ----------
__global__ void k_scan1(const float* __restrict__ loglam)
{
    const int idx   = blockIdx.x * blockDim.x + threadIdx.x;  // 0..32767
    const int s     = idx & (Sq - 1);
    const int b     = (idx >> 8) & 1;
    const int chunk = idx >> 9;
    const float lam = 1.f / (1.f + expf(-loglam[s]));
    float* p = g_bu + ((size_t)(b * Tq + chunk * CLEN)) * Sq + s;
    float h = 0.f;
    float buf[4];
#pragma unroll
    for (int j = 0; j < 4; j++) buf[j] = p[(size_t)j * Sq];
#pragma unroll
    for (int j0 = 0; j0 < CLEN; j0 += 4) {
        float c0 = buf[0], c1 = buf[1], c2 = buf[2], c3 = buf[3];
        if (j0 + 4 < CLEN) {
#pragma unroll
            for (int j = 0; j < 4; j++) buf[j] = p[(size_t)(j0 + 4 + j) * Sq];
        }
        h = fmaf(lam, h, c0); p[(size_t)(j0 + 0) * Sq] = h;
        h = fmaf(lam, h, c1); p[(size_t)(j0 + 1) * Sq] = h;
        h = fmaf(lam, h, c2); p[(size_t)(j0 + 2) * Sq] = h;
        h = fmaf(lam, h, c3); p[(size_t)(j0 + 3) * Sq] = h;
    }
    g_carry[((size_t)b * Sq + s) * NCHUNK + chunk] = h;
}

__global__ void k_scan2(const float* __restrict__ loglam)
{
    const int idx = blockIdx.x * blockDim.x + threadIdx.x;    // 0..511
    const int s = idx & (Sq - 1);
    const int b = idx >> 8;
    const float lam = 1.f / (1.f + expf(-loglam[s]));
    float lp = lam;
#pragma unroll
    for (int i = 0; i < 5; i++) lp *= lp;    // lam^32
    float* cb = g_carry + ((size_t)b * Sq + s) * NCHUNK;
    float H = 0.f;
#pragma unroll
    for (int c = 0; c < NCHUNK; c++) {
        float carry = cb[c];
        cb[c] = H;
        H = fmaf(lp, H, carry);
    }
}

// fixup + fp16 conversion (all chunks)
__global__ void k_scan3(const float* __restrict__ loglam)
{
    const int idx   = blockIdx.x * blockDim.x + threadIdx.x;
    const int s     = idx & (Sq - 1);
    const int b     = (idx >> 8) & 1;
    const int chunk = idx >> 9;
    const float lam = 1.f / (1.f + expf(-loglam[s]));
    const float H = g_carry[((size_t)b * Sq + s) * NCHUNK + chunk];
    const size_t base = ((size_t)(b * Tq + chunk * CLEN)) * Sq + s;
    const float* p = g_bu + base;
    __half* ph = g_buh + base;
    float f = lam;
#pragma unroll
    for (int j0 = 0; j0 < CLEN; j0 += 8) {
        float v[8];
#pragma unroll
        for (int u = 0; u < 8; u++) v[u] = p[(size_t)(j0 + u) * Sq];
#pragma unroll
        for (int u = 0; u < 8; u++) { v[u] += f * H; f *= lam; }
#pragma unroll
        for (int u = 0; u < 8; u++) ph[(size_t)(j0 + u) * Sq] = __float2half_rn(v[u]);
    }
}

// ---------------- orchestration ----------------
extern "C" void kernel_launch(void* const* d_in, const int* in_sizes, int n_in,
                              void* d_out, int out_size)
{
    const int*   x      = (const int*)  d_in[0];
    const float* emb    = (const float*)d_in[1];
    const float* pos    = (const float*)d_in[2];
    const float* loglam = (const float*)d_in[3];
    const float* Bw     = (const float*)d_in[4];
    const float* Cw     = (const float*)d_in[5];
    const float* Dp     = (const float*)d_in[6];
    const float* n1w    = (const float*)d_in[7];
    const float* n1b    = (const float*)d_in[8];
    const float* n2w    = (const float*)d_in[9];
    const float* n2b    = (const float*)d_in[10];
    const float* w1     = (const float*)d_in[11];
    const float* w2     = (const float*)d_in[12];
    const float* w3     = (const float*)d_in[13];
    const float* now    = (const float*)d_in[14];
    const float* nob    = (const float*)d_in[15];
    const float* headW  = (const float*)d_in[16];
    const float* headb  = (const float*)d_in[17];
    float* out = (float*)d_out;

    void *ph, *pb, *pf, *plh, *pbh, *pfh, *pw;
    cudaGetSymbolAddress(&ph,  g_h);
    cudaGetSymbolAddress(&pb,  g_bu);
    cudaGetSymbolAddress(&pf,  g_ff);
    cudaGetSymbolAddress(&plh, g_lnh);
    cudaGetSymbolAddress(&pbh, g_buh);
    cudaGetSymbolAddress(&pfh, g_ffh);
    cudaGetSymbolAddress(&pw,  g_w);
    float*  h   = (float*)ph;
    float*  bu  = (float*)pb;
    float*  ff  = (float*)pf;
    __half* lnh = (__half*)plh;
    __half* buh = (__half*)pbh;
    __half* ffh = (__half*)pfh;
    __half* gw  = (__half*)pw;

    cudaFuncSetAttribute(k_mma<0>, cudaFuncAttributeMaxDynamicSharedMemorySize, SMEM_MMA);
    cudaFuncSetAttribute(k_mma<1>, cudaFuncAttributeMaxDynamicSharedMemorySize, SMEM_MMA);
    cudaFuncSetAttribute(k_mma<2>, cudaFuncAttributeMaxDynamicSharedMemorySize, SMEM_MMA);
    cudaFuncSetAttribute(k_mma<3>, cudaFuncAttributeMaxDynamicSharedMemorySize, SMEM_MMA);
    cudaFuncSetAttribute(k_mma<4>, cudaFuncAttributeMaxDynamicSharedMemorySize, SMEM_MMA);

    // ---- weight conversion (once per launch) ----
    k_cvt<<<CNT_HEAD / 8 / 256, 256>>>(headW, gw + OFF_HEAD, CNT_HEAD / 8);
    k_cvt<<<CNT_BW   / 8 / 256, 256>>>(Bw,    gw + OFF_BW,   CNT_BW   / 8);
    k_cvt<<<CNT_BW   / 8 / 256, 256>>>(Cw,    gw + OFF_CW,   CNT_BW   / 8);
    k_cvt<<<CNT_W    / 8 / 256, 256>>>(w1,    gw + OFF_W1,   CNT_W    / 8);
    k_cvt<<<CNT_W    / 8 / 256, 256>>>(w2,    gw + OFF_W2,   CNT_W    / 8);
    k_cvt<<<CNT_W    / 8 / 256, 256>>>(w3,    gw + OFF_W3,   CNT_W    / 8);

    const dim3 gBu(BT / 128, Sq / 128);
    const dim3 gC (BT / 128, Dq / 128);
    const dim3 gFF(BT / 128, (DFFq + 127) / 128);
    const dim3 gW3(BT / 128, Dq / 128);
    const dim3 gHd(BT / 128, Vq / 128);

    k_embed<<<BT, 128>>>(x, emb, pos);

    const int lBw = Sq * Dq;            // per-layer weight strides (halfs)
    const int lW  = DFFq * Dq;

    for (int l = 0; l < Lq; l++) {
        // ---- SSM block ----
        k_ln<<<BT, 128>>>(h, lnh, n1w + l * Dq, n1b + l * Dq);
        k_mma<0><<<gBu, 256, SMEM_MMA>>>(lnh, gw + OFF_BW + (size_t)l * lBw,
                                         bu, nullptr, BT, Sq, Dq, nullptr, nullptr);
        k_scan1<<<128, 256>>>(loglam + l * Sq);
        k_scan2<<<2, 256>>>(loglam + l * Sq);
        k_scan3<<<128, 256>>>(loglam + l * Sq);
        k_mma<2><<<gC, 256, SMEM_MMA>>>(buh, gw + OFF_CW + (size_t)l * lBw,
                                        h, nullptr, BT, Dq, Sq, Dp + l * Dq, lnh);
        // ---- SwiGLU block ----
        k_ln<<<BT, 128>>>(h, lnh, n2w + l * Dq, n2b + l * Dq);
        k_mma<0><<<gFF, 256, SMEM_MMA>>>(lnh, gw + OFF_W1 + (size_t)l * lW,
                                         ff, nullptr, BT, DFFq, Dq, nullptr, nullptr);
        k_mma<1><<<gFF, 256, SMEM_MMA>>>(lnh, gw + OFF_W2 + (size_t)l * lW,
                                         ff, ffh, BT, DFFq, Dq, nullptr, nullptr);
        k_mma<3><<<gW3, 256, SMEM_MMA>>>(ffh, gw + OFF_W3 + (size_t)l * lW,
                                         h, nullptr, BT, Dq, DFFq, nullptr, nullptr);
    }

    // ---- head ----
    k_ln<<<BT, 128>>>(h, lnh, now, nob);
    k_mma<4><<<gHd, 256, SMEM_MMA>>>(lnh, gw + OFF_HEAD,
                                     out, nullptr, BT, Vq, Dq, headb, nullptr);
}

// round 12
// speedup vs baseline: 7.3456x; 1.1569x over previous
#include <cuda_runtime.h>
#include <cuda_fp16.h>
#include <math.h>
#include <stdint.h>

#define Bq    2
#define Tq    2048
#define BT    4096
#define Dq    512
#define Sq    256
#define Lq    4
#define DFFq  1368
#define Vq    32000
#define EPSq  1e-5f
#define NCHUNK 64
#define CLEN   32    // Tq / NCHUNK

// ---------------- fp32 scratch ----------------
__device__ __align__(128) float g_h [(size_t)BT * Dq];    // residual stream
__device__ __align__(128) float g_bu[(size_t)BT * Sq];    // Bu (fp32, scan in place)
__device__ __align__(128) float g_carry[Bq * Sq * NCHUNK];

// ---------------- fp16 scratch ----------------
__device__ __align__(128) __half g_lnh[(size_t)BT * Dq];   // LN output (A operand)
__device__ __align__(128) __half g_buh[(size_t)BT * Sq];   // scanned h (A operand)
__device__ __align__(128) __half g_ffh[(size_t)BT * DFFq]; // gated product (A operand)

// ---------------- fp16 weight arena ----------------
#define CNT_HEAD (Vq * Dq)                 // 16384000
#define CNT_BW   (Lq * Sq * Dq)            // 524288
#define CNT_W    (Lq * DFFq * Dq)          // 2801664
#define OFF_HEAD 0
#define OFF_BW   (OFF_HEAD + CNT_HEAD)
#define OFF_CW   (OFF_BW + CNT_BW)
#define OFF_W12  (OFF_CW + CNT_BW)         // interleaved w1/w2: 2*CNT_W
#define OFF_W3   (OFF_W12 + 2 * CNT_W)
#define GW_TOTAL (OFF_W3 + CNT_W)
__device__ __align__(128) __half g_w[(size_t)GW_TOTAL];

// ---------------- helpers ----------------
__device__ __forceinline__ uint32_t pack_h2(float x, float y) {
    __half2 h = __floats2half2_rn(x, y);
    return *(uint32_t*)&h;
}
__device__ __forceinline__ void ldm_x4(uint32_t* r, uint32_t addr) {
    asm volatile("ldmatrix.sync.aligned.m8n8.x4.shared.b16 {%0,%1,%2,%3}, [%4];"
                 : "=r"(r[0]), "=r"(r[1]), "=r"(r[2]), "=r"(r[3]) : "r"(addr));
}
__device__ __forceinline__ void mma_f16(float* c, const uint32_t* a, uint32_t b0, uint32_t b1) {
    asm volatile(
        "mma.sync.aligned.m16n8k16.row.col.f32.f16.f16.f32 "
        "{%0,%1,%2,%3}, {%4,%5,%6,%7}, {%8,%9}, {%0,%1,%2,%3};"
        : "+f"(c[0]), "+f"(c[1]), "+f"(c[2]), "+f"(c[3])
        : "r"(a[0]), "r"(a[1]), "r"(a[2]), "r"(a[3]), "r"(b0), "r"(b1));
}
__device__ __forceinline__ void cp16(uint32_t dst, const void* src, int sz) {
    asm volatile("cp.async.cg.shared.global [%0], [%1], 16, %2;"
                 :: "r"(dst), "l"(src), "r"(sz) : "memory");
}
#define CP_COMMIT() asm volatile("cp.async.commit_group;" ::: "memory")
#define CP_WAIT1()  asm volatile("cp.async.wait_group 1;" ::: "memory")
#define CP_WAIT0()  asm volatile("cp.async.wait_group 0;" ::: "memory")

// ---------------- weight converts (fp32 -> fp16) ----------------
__global__ void k_cvt(const float* __restrict__ s, __half* __restrict__ d, int n8)
{
    const int i = blockIdx.x * blockDim.x + threadIdx.x;
    if (i >= n8) return;
    float4 a = ((const float4*)s)[2 * i];
    float4 b = ((const float4*)s)[2 * i + 1];
    uint4 o;
    o.x = pack_h2(a.x, a.y); o.y = pack_h2(a.z, a.w);
    o.z = pack_h2(b.x, b.y); o.w = pack_h2(b.z, b.w);
    ((uint4*)d)[i] = o;
}

// interleave w1/w2 rows per layer: dst row (l, 2f) = w1[l,f], (l, 2f+1) = w2[l,f]
__global__ void k_cvt2(const float* __restrict__ w1, const float* __restrict__ w2,
                       __half* __restrict__ d, int n8)
{
    const int i = blockIdx.x * blockDim.x + threadIdx.x;
    if (i >= n8) return;
    const int fg  = i >> 6;              // global row over L*DFF (Dq/8 = 64 groups/row)
    const int off = (i & 63) * 8;
    const int l   = fg / DFFq;
    const int f   = fg - l * DFFq;
    const float4* s1 = (const float4*)(w1 + (size_t)fg * Dq + off);
    const float4* s2 = (const float4*)(w2 + (size_t)fg * Dq + off);
    __half* dst = d + ((size_t)l * 2 * DFFq + 2 * f) * Dq + off;
    float4 a = s1[0], b = s1[1];
    uint4 o;
    o.x = pack_h2(a.x, a.y); o.y = pack_h2(a.z, a.w);
    o.z = pack_h2(b.x, b.y); o.w = pack_h2(b.z, b.w);
    *(uint4*)dst = o;
    a = s2[0]; b = s2[1];
    o.x = pack_h2(a.x, a.y); o.y = pack_h2(a.z, a.w);
    o.z = pack_h2(b.x, b.y); o.w = pack_h2(b.z, b.w);
    *(uint4*)(dst + Dq) = o;
}

// ---------------- embedding: h = emb[x] + pos[t] ----------------
__global__ void k_embed(const int* __restrict__ x, const float* __restrict__ emb,
                        const float* __restrict__ pos)
{
    const int row = blockIdx.x;
    const int t   = row & (Tq - 1);
    const int tok = x[row];
    const float4* e = (const float4*)(emb + (size_t)tok * Dq);
    const float4* p = (const float4*)(pos + (size_t)t * Dq);
    float4* o = (float4*)(g_h + (size_t)row * Dq);
    const int c = threadIdx.x;
    float4 a = e[c], b = p[c];
    o[c] = make_float4(a.x + b.x, a.y + b.y, a.z + b.z, a.w + b.w);
}

// ---------------- layernorm: fp32 in -> fp16 out ----------------
__global__ void k_ln(const float* __restrict__ in, __half* __restrict__ out,
                     const float* __restrict__ w, const float* __restrict__ b)
{
    const int row = blockIdx.x;
    const int c = threadIdx.x;
    const float4 v = ((const float4*)(in + (size_t)row * Dq))[c];
    float s  = v.x + v.y + v.z + v.w;
    float ss = v.x*v.x + v.y*v.y + v.z*v.z + v.w*v.w;
#pragma unroll
    for (int o = 16; o > 0; o >>= 1) {
        s  += __shfl_xor_sync(0xffffffffu, s,  o);
        ss += __shfl_xor_sync(0xffffffffu, ss, o);
    }
    __shared__ float sm[10];
    const int wid = c >> 5;
    if ((c & 31) == 0) { sm[wid] = s; sm[4 + wid] = ss; }
    __syncthreads();
    if (c == 0) {
        float S1 = sm[0] + sm[1] + sm[2] + sm[3];
        float S2 = sm[4] + sm[5] + sm[6] + sm[7];
        float mu  = S1 * (1.0f / Dq);
        float var = S2 * (1.0f / Dq) - mu * mu;
        sm[8] = mu;
        sm[9] = rsqrtf(var + EPSq);
    }
    __syncthreads();
    const float mu = sm[8], rs = sm[9];
    const float4 wv = ((const float4*)w)[c];
    const float4 bv = ((const float4*)b)[c];
    uint2 o;
    o.x = pack_h2((v.x - mu) * rs * wv.x + bv.x, (v.y - mu) * rs * wv.y + bv.y);
    o.y = pack_h2((v.z - mu) * rs * wv.z + bv.z, (v.w - mu) * rs * wv.w + bv.w);
    ((uint2*)(out + (size_t)row * Dq))[c] = o;
}

// =================== fp16 mma GEMM: C = A[M,K]*B[N,K]^T (half inputs) ===========
// CTA tile MT x 128 (MT = 128 or 64), BK=64, 3-stage cp.async, 256 threads.
// 8 warps in 2(m) x 4(n); warp tile (MT/2) x 32.
// MODE 0: C = acc                              (fp32 out)
// MODE 1: fused SwiGLU, interleaved N=2*DFF:   Ch[m][n>>1] = silu(g)*v
// MODE 2: C = C + acc + aux1[n]*aux2h[m,n]     (SSM residual)
// MODE 3: C = C + acc                          (FFN residual)
// MODE 4: C = acc + aux1[n]                    (head bias)
template<int MODE, int MT>
__global__ void __launch_bounds__(256, 2)
k_mma(const __half* __restrict__ A, const __half* __restrict__ Bm,
      float* __restrict__ C, __half* __restrict__ Ch, int M, int N, int K,
      const float* __restrict__ aux1, const __half* __restrict__ aux2)
{
    constexpr int MI   = MT / 32;        // m16 frags per warp / A staging iters
    constexpr uint32_t ASTG = (uint32_t)MT * 128;
    constexpr uint32_t BOFF = 3 * ASTG;
    constexpr int WMR  = MT / 2;         // warp m rows

    extern __shared__ char smem[];
    const uint32_t sb = (uint32_t)__cvta_generic_to_shared(smem);

    const int tid  = threadIdx.x;
    const int wid  = tid >> 5;
    const int lane = tid & 31;
    const int gid  = lane >> 2;
    const int tig  = lane & 3;
    const int hi   = lane >> 4;
    const int lrow = lane & 15;
    const int rswz = lrow & 7;
    const int wm   = wid & 1;
    const int wn   = wid >> 1;
    const int bm   = blockIdx.x * MT;
    const int bn   = blockIdx.y * 128;

    const int r0  = tid >> 3;            // 0..31
    const int c16 = tid & 7;             // 0..7
    const uint32_t swz16 = (uint32_t)((c16 ^ (r0 & 7)) * 16);
    const __half* Asrc = A  + (size_t)(bm + r0) * K + c16 * 8;
    const __half* Bsrc = Bm + (size_t)(bn + r0) * K + c16 * 8;

    float acc[MI][4][4];
#pragma unroll
    for (int i = 0; i < MI; i++)
#pragma unroll
        for (int j = 0; j < 4; j++)
#pragma unroll
            for (int q = 0; q < 4; q++) acc[i][j][q] = 0.f;

    const int nk = (K + 63) >> 6;

    auto issue = [&](int kc) {
        const uint32_t sta = (uint32_t)(kc % 3) * ASTG;
        const uint32_t stb = BOFF + (uint32_t)(kc % 3) * 16384u;
        const int k0 = kc << 6;
        const int ksz = (k0 + c16 * 8 + 8 <= K) ? 16 : 0;
#pragma unroll
        for (int i = 0; i < MI; i++) {
            const uint32_t dof = (uint32_t)((i * 32 + r0) * 128) + swz16;
            cp16(sb + sta + dof, Asrc + (size_t)(i * 32) * K + k0, ksz);
        }
#pragma unroll
        for (int i = 0; i < 4; i++) {
            const uint32_t dof = (uint32_t)((i * 32 + r0) * 128) + swz16;
            const int bsz = ((bn + i * 32 + r0) < N) ? ksz : 0;
            cp16(sb + stb + dof, Bsrc + (size_t)(i * 32) * K + k0, bsz);
        }
        CP_COMMIT();
    };

    issue(0);
    issue(1);

    for (int kch = 0; kch < nk; kch++) {
        CP_WAIT1();
        __syncthreads();
        if (kch + 2 < nk) issue(kch + 2);

        const uint32_t arow = sb + (uint32_t)(kch % 3) * ASTG
                              + (uint32_t)((wm * WMR + lrow) * 128);
        const uint32_t brow = sb + BOFF + (uint32_t)(kch % 3) * 16384u
                              + (uint32_t)((wn * 32 + lrow) * 128);
#pragma unroll
        for (int ks = 0; ks < 4; ks++) {
            const uint32_t csw = (uint32_t)(((ks * 2 + hi) ^ rswz) * 16);
            uint32_t afr[MI][4];
#pragma unroll
            for (int mi = 0; mi < MI; mi++)
                ldm_x4(afr[mi], arow + (uint32_t)(mi * 16 * 128) + csw);
            uint32_t bfr[2][4];
#pragma unroll
            for (int nj = 0; nj < 2; nj++)
                ldm_x4(bfr[nj], brow + (uint32_t)(nj * 16 * 128) + csw);
#pragma unroll
            for (int mi = 0; mi < MI; mi++)
#pragma unroll
                for (int ni = 0; ni < 4; ni++) {
                    const int nj = ni >> 1, h = ni & 1;
                    mma_f16(acc[mi][ni], afr[mi], bfr[nj][h], bfr[nj][h + 2]);
                }
        }
        __syncthreads();
    }
    CP_WAIT0();

    // ---- epilogue ----
#pragma unroll
    for (int mi = 0; mi < MI; mi++) {
        const int r0m = bm + wm * WMR + mi * 16 + gid;
#pragma unroll
        for (int half = 0; half < 2; half++) {
            const int m = r0m + half * 8;
            const size_t rowoff = (size_t)m * N;
#pragma unroll
            for (int ni = 0; ni < 4; ni++) {
                const int n0 = bn + wn * 32 + ni * 8;
                if (n0 >= N) continue;
                const int n = n0 + tig * 2;
                float2 rv;
                rv.x = acc[mi][ni][half * 2 + 0];
                rv.y = acc[mi][ni][half * 2 + 1];
                if (MODE == 0) {
                    *(float2*)(C + rowoff + n) = rv;
                } else if (MODE == 1) {
                    // interleaved fused SwiGLU: rv = (gate, value)
                    const int f = n >> 1;
                    float r = rv.y * rv.x / (1.f + __expf(-rv.x));
                    Ch[(size_t)m * DFFq + f] = __float2half_rn(r);
                } else if (MODE == 2) {
                    float2* cp = (float2*)(C + rowoff + n);
                    float2 c  = *cp;
                    float2 dp = *(const float2*)(aux1 + n);
                    float2 u  = __half22float2(*(const __half2*)(aux2 + rowoff + n));
                    rv.x += c.x + dp.x * u.x;
                    rv.y += c.y + dp.y * u.y;
                    *cp = rv;
                } else if (MODE == 3) {
                    float2* cp = (float2*)(C + rowoff + n);
                    float2 c = *cp;
                    rv.x += c.x; rv.y += c.y;
                    *cp = rv;
                } else {
                    float2 bb = *(const float2*)(aux1 + n);
                    rv.x += bb.x; rv.y += bb.y;
                    *(float2*)(C + rowoff + n) = rv;
                }
            }
        }
    }
}

#define SMEM64  73728
#define SMEM128 98304

// ---------------- SSM scan: h[t] = lam*h[t-1] + Bu[t], 64 chunks of 32 ----------
__global__ void k_scan1(const float* __restrict__ loglam)
{
    const int idx   = blockIdx.x * blockDim.x + threadIdx.x;
    const int s     = idx & (Sq - 1);
    const int b     = (idx >> 8) & 1;
    const int chunk = idx >> 9;
    const float lam = 1.f / (1.f + expf(-loglam[s]));
    float* p = g_bu + ((size_t)(b * Tq + chunk * CLEN)) * Sq + s;
    float h = 0.f;
    float buf[4];
#pragma unroll
    for (int j = 0; j < 4; j++) buf[j] = p[(size_t)j * Sq];
#pragma unroll
    for (int j0 = 0; j0 < CLEN; j0 += 4) {
        float c0 = buf[0], c1 = buf[1], c2 = buf[2], c3 = buf[3];
        if (j0 + 4 < CLEN) {
#pragma unroll
            for (int j = 0; j < 4; j++) buf[j] = p[(size_t)(j0 + 4 + j) * Sq];
        }
        h = fmaf(lam, h, c0); p[(size_t)(j0 + 0) * Sq] = h;
        h = fmaf(lam, h, c1); p[(size_t)(j0 + 1) * Sq] = h;
        h = fmaf(lam, h, c2); p[(size_t)(j0 + 2) * Sq] = h;
        h = fmaf(lam, h, c3); p[(size_t)(j0 + 3) * Sq] = h;
    }
    g_carry[((size_t)b * Sq + s) * NCHUNK + chunk] = h;
}

__global__ void k_scan2(const float* __restrict__ loglam)
{
    const int idx = blockIdx.x * blockDim.x + threadIdx.x;
    const int s = idx & (Sq - 1);
    const int b = idx >> 8;
    const float lam = 1.f / (1.f + expf(-loglam[s]));
    float lp = lam;
#pragma unroll
    for (int i = 0; i < 5; i++) lp *= lp;    // lam^32
    float* cb = g_carry + ((size_t)b * Sq + s) * NCHUNK;
    float H = 0.f;
#pragma unroll
    for (int c = 0; c < NCHUNK; c++) {
        float carry = cb[c];
        cb[c] = H;
        H = fmaf(lp, H, carry);
    }
}

__global__ void k_scan3(const float* __restrict__ loglam)
{
    const int idx   = blockIdx.x * blockDim.x + threadIdx.x;
    const int s     = idx & (Sq - 1);
    const int b     = (idx >> 8) & 1;
    const int chunk = idx >> 9;
    const float lam = 1.f / (1.f + expf(-loglam[s]));
    const float H = g_carry[((size_t)b * Sq + s) * NCHUNK + chunk];
    const size_t base = ((size_t)(b * Tq + chunk * CLEN)) * Sq + s;
    const float* p = g_bu + base;
    __half* ph = g_buh + base;
    float f = lam;
#pragma unroll
    for (int j0 = 0; j0 < CLEN; j0 += 8) {
        float v[8];
#pragma unroll
        for (int u = 0; u < 8; u++) v[u] = p[(size_t)(j0 + u) * Sq];
#pragma unroll
        for (int u = 0; u < 8; u++) { v[u] += f * H; f *= lam; }
#pragma unroll
        for (int u = 0; u < 8; u++) ph[(size_t)(j0 + u) * Sq] = __float2half_rn(v[u]);
    }
}

// ---------------- orchestration ----------------
extern "C" void kernel_launch(void* const* d_in, const int* in_sizes, int n_in,
                              void* d_out, int out_size)
{
    const int*   x      = (const int*)  d_in[0];
    const float* emb    = (const float*)d_in[1];
    const float* pos    = (const float*)d_in[2];
    const float* loglam = (const float*)d_in[3];
    const float* Bw     = (const float*)d_in[4];
    const float* Cw     = (const float*)d_in[5];
    const float* Dp     = (const float*)d_in[6];
    const float* n1w    = (const float*)d_in[7];
    const float* n1b    = (const float*)d_in[8];
    const float* n2w    = (const float*)d_in[9];
    const float* n2b    = (const float*)d_in[10];
    const float* w1     = (const float*)d_in[11];
    const float* w2     = (const float*)d_in[12];
    const float* w3     = (const float*)d_in[13];
    const float* now    = (const float*)d_in[14];
    const float* nob    = (const float*)d_in[15];
    const float* headW  = (const float*)d_in[16];
    const float* headb  = (const float*)d_in[17];
    float* out = (float*)d_out;

    void *ph, *pb, *plh, *pbh, *pfh, *pw;
    cudaGetSymbolAddress(&ph,  g_h);
    cudaGetSymbolAddress(&pb,  g_bu);
    cudaGetSymbolAddress(&plh, g_lnh);
    cudaGetSymbolAddress(&pbh, g_buh);
    cudaGetSymbolAddress(&pfh, g_ffh);
    cudaGetSymbolAddress(&pw,  g_w);
    float*  h   = (float*)ph;
    float*  bu  = (float*)pb;
    __half* lnh = (__half*)plh;
    __half* buh = (__half*)pbh;
    __half* ffh = (__half*)pfh;
    __half* gw  = (__half*)pw;

    cudaFuncSetAttribute(k_mma<0,64>,  cudaFuncAttributeMaxDynamicSharedMemorySize, SMEM64);
    cudaFuncSetAttribute(k_mma<2,64>,  cudaFuncAttributeMaxDynamicSharedMemorySize, SMEM64);
    cudaFuncSetAttribute(k_mma<3,64>,  cudaFuncAttributeMaxDynamicSharedMemorySize, SMEM64);
    cudaFuncSetAttribute(k_mma<1,128>, cudaFuncAttributeMaxDynamicSharedMemorySize, SMEM128);
    cudaFuncSetAttribute(k_mma<4,128>, cudaFuncAttributeMaxDynamicSharedMemorySize, SMEM128);

    // ---- weight conversion (once per launch) ----
    k_cvt <<<8000, 256>>>(headW, gw + OFF_HEAD, CNT_HEAD / 8);
    k_cvt <<<256,  256>>>(Bw,    gw + OFF_BW,   CNT_BW / 8);
    k_cvt <<<256,  256>>>(Cw,    gw + OFF_CW,   CNT_BW / 8);
    k_cvt2<<<1368, 256>>>(w1, w2, gw + OFF_W12, CNT_W / 8);
    k_cvt <<<1368, 256>>>(w3,    gw + OFF_W3,   CNT_W / 8);

    const dim3 gBu(BT / 64, Sq / 128);                    // 64 x 2
    const dim3 gC (BT / 64, Dq / 128);                    // 64 x 4
    const dim3 gW12(BT / 128, (2 * DFFq + 127) / 128);    // 32 x 22
    const dim3 gW3(BT / 64, Dq / 128);                    // 64 x 4
    const dim3 gHd(BT / 128, Vq / 128);                   // 32 x 250

    k_embed<<<BT, 128>>>(x, emb, pos);

    const int lBw = Sq * Dq;
    for (int l = 0; l < Lq; l++) {
        // ---- SSM block ----
        k_ln<<<BT, 128>>>(h, lnh, n1w + l * Dq, n1b + l * Dq);
        k_mma<0,64><<<gBu, 256, SMEM64>>>(lnh, gw + OFF_BW + (size_t)l * lBw,
                                          bu, nullptr, BT, Sq, Dq, nullptr, nullptr);
        k_scan1<<<128, 256>>>(loglam + l * Sq);
        k_scan2<<<2, 256>>>(loglam + l * Sq);
        k_scan3<<<128, 256>>>(loglam + l * Sq);
        k_mma<2,64><<<gC, 256, SMEM64>>>(buh, gw + OFF_CW + (size_t)l * lBw,
                                         h, nullptr, BT, Dq, Sq, Dp + l * Dq, lnh);
        // ---- SwiGLU block (fused w1+w2 interleaved) ----
        k_ln<<<BT, 128>>>(h, lnh, n2w + l * Dq, n2b + l * Dq);
        k_mma<1,128><<<gW12, 256, SMEM128>>>(lnh, gw + OFF_W12 + (size_t)l * 2 * DFFq * Dq,
                                             nullptr, ffh, BT, 2 * DFFq, Dq, nullptr, nullptr);
        k_mma<3,64><<<gW3, 256, SMEM64>>>(ffh, gw + OFF_W3 + (size_t)l * DFFq * Dq,
                                          h, nullptr, BT, Dq, DFFq, nullptr, nullptr);
    }

    // ---- head ----
    k_ln<<<BT, 128>>>(h, lnh, now, nob);
    k_mma<4,128><<<gHd, 256, SMEM128>>>(lnh, gw + OFF_HEAD,
                                        out, nullptr, BT, Vq, Dq, headb, nullptr);
}

// round 13
// speedup vs baseline: 7.5114x; 1.0226x over previous
#include <cuda_runtime.h>
#include <cuda_fp16.h>
#include <math.h>
#include <stdint.h>

#define Bq    2
#define Tq    2048
#define BT    4096
#define Dq    512
#define Sq    256
#define Lq    4
#define DFFq  1368
#define Vq    32000
#define EPSq  1e-5f
#define NCHUNK 64
#define CLEN   32    // Tq / NCHUNK

// ---------------- fp32 scratch ----------------
__device__ __align__(128) float g_h [(size_t)BT * Dq];    // residual stream
__device__ __align__(128) float g_bu[(size_t)BT * Sq];    // Bu (fp32, scan in place)
__device__ __align__(128) float g_carry[NCHUNK * Bq * Sq]; // [chunk][b][s]

// ---------------- fp16 scratch ----------------
__device__ __align__(128) __half g_lnh[(size_t)BT * Dq];   // LN output (A operand)
__device__ __align__(128) __half g_buh[(size_t)BT * Sq];   // scanned h (A operand)
__device__ __align__(128) __half g_ffh[(size_t)BT * DFFq]; // gated product (A operand)

// ---------------- fp16 weight arena ----------------
#define CNT_HEAD (Vq * Dq)
#define CNT_BW   (Lq * Sq * Dq)
#define CNT_W    (Lq * DFFq * Dq)
#define OFF_HEAD 0
#define OFF_BW   (OFF_HEAD + CNT_HEAD)
#define OFF_CW   (OFF_BW + CNT_BW)
#define OFF_W12  (OFF_CW + CNT_BW)         // interleaved w1/w2: 2*CNT_W
#define OFF_W3   (OFF_W12 + 2 * CNT_W)
#define GW_TOTAL (OFF_W3 + CNT_W)
__device__ __align__(128) __half g_w[(size_t)GW_TOTAL];

// ---------------- helpers ----------------
__device__ __forceinline__ uint32_t pack_h2(float x, float y) {
    __half2 h = __floats2half2_rn(x, y);
    return *(uint32_t*)&h;
}
__device__ __forceinline__ void ldm_x4(uint32_t* r, uint32_t addr) {
    asm volatile("ldmatrix.sync.aligned.m8n8.x4.shared.b16 {%0,%1,%2,%3}, [%4];"
                 : "=r"(r[0]), "=r"(r[1]), "=r"(r[2]), "=r"(r[3]) : "r"(addr));
}
__device__ __forceinline__ void mma_f16(float* c, const uint32_t* a, uint32_t b0, uint32_t b1) {
    asm volatile(
        "mma.sync.aligned.m16n8k16.row.col.f32.f16.f16.f32 "
        "{%0,%1,%2,%3}, {%4,%5,%6,%7}, {%8,%9}, {%0,%1,%2,%3};"
        : "+f"(c[0]), "+f"(c[1]), "+f"(c[2]), "+f"(c[3])
        : "r"(a[0]), "r"(a[1]), "r"(a[2]), "r"(a[3]), "r"(b0), "r"(b1));
}
__device__ __forceinline__ void cp16(uint32_t dst, const void* src, int sz) {
    asm volatile("cp.async.cg.shared.global [%0], [%1], 16, %2;"
                 :: "r"(dst), "l"(src), "r"(sz) : "memory");
}
#define CP_COMMIT() asm volatile("cp.async.commit_group;" ::: "memory")
#define CP_WAIT1()  asm volatile("cp.async.wait_group 1;" ::: "memory")
#define CP_WAIT0()  asm volatile("cp.async.wait_group 0;" ::: "memory")

// ---------------- weight converts (fp32 -> fp16) ----------------
__global__ void k_cvt(const float* __restrict__ s, __half* __restrict__ d, int n8)
{
    const int i = blockIdx.x * blockDim.x + threadIdx.x;
    if (i >= n8) return;
    float4 a = ((const float4*)s)[2 * i];
    float4 b = ((const float4*)s)[2 * i + 1];
    uint4 o;
    o.x = pack_h2(a.x, a.y); o.y = pack_h2(a.z, a.w);
    o.z = pack_h2(b.x, b.y); o.w = pack_h2(b.z, b.w);
    ((uint4*)d)[i] = o;
}

// interleave w1/w2 rows per layer: dst row (l, 2f) = w1[l,f], (l, 2f+1) = w2[l,f]
__global__ void k_cvt2(const float* __restrict__ w1, const float* __restrict__ w2,
                       __half* __restrict__ d, int n8)
{
    const int i = blockIdx.x * blockDim.x + threadIdx.x;
    if (i >= n8) return;
    const int fg  = i >> 6;
    const int off = (i & 63) * 8;
    const int l   = fg / DFFq;
    const int f   = fg - l * DFFq;
    const float4* s1 = (const float4*)(w1 + (size_t)fg * Dq + off);
    const float4* s2 = (const float4*)(w2 + (size_t)fg * Dq + off);
    __half* dst = d + ((size_t)l * 2 * DFFq + 2 * f) * Dq + off;
    float4 a = s1[0], b = s1[1];
    uint4 o;
    o.x = pack_h2(a.x, a.y); o.y = pack_h2(a.z, a.w);
    o.z = pack_h2(b.x, b.y); o.w = pack_h2(b.z, b.w);
    *(uint4*)dst = o;
    a = s2[0]; b = s2[1];
    o.x = pack_h2(a.x, a.y); o.y = pack_h2(a.z, a.w);
    o.z = pack_h2(b.x, b.y); o.w = pack_h2(b.z, b.w);
    *(uint4*)(dst + Dq) = o;
}

// ---------------- LN core (128 threads, one row of 512) ----------------
__device__ __forceinline__ void ln_row(const float4 v, const float* w, const float* b,
                                       __half* out_row, int c)
{
    float s  = v.x + v.y + v.z + v.w;
    float ss = v.x*v.x + v.y*v.y + v.z*v.z + v.w*v.w;
#pragma unroll
    for (int o = 16; o > 0; o >>= 1) {
        s  += __shfl_xor_sync(0xffffffffu, s,  o);
        ss += __shfl_xor_sync(0xffffffffu, ss, o);
    }
    __shared__ float sm[10];
    const int wid = c >> 5;
    if ((c & 31) == 0) { sm[wid] = s; sm[4 + wid] = ss; }
    __syncthreads();
    if (c == 0) {
        float S1 = sm[0] + sm[1] + sm[2] + sm[3];
        float S2 = sm[4] + sm[5] + sm[6] + sm[7];
        float mu  = S1 * (1.0f / Dq);
        float var = S2 * (1.0f / Dq) - mu * mu;
        sm[8] = mu;
        sm[9] = rsqrtf(var + EPSq);
    }
    __syncthreads();
    const float mu = sm[8], rs = sm[9];
    const float4 wv = ((const float4*)w)[c];
    const float4 bv = ((const float4*)b)[c];
    uint2 o;
    o.x = pack_h2((v.x - mu) * rs * wv.x + bv.x, (v.y - mu) * rs * wv.y + bv.y);
    o.y = pack_h2((v.z - mu) * rs * wv.z + bv.z, (v.w - mu) * rs * wv.w + bv.w);
    ((uint2*)out_row)[c] = o;
}

// ---------------- fused embedding + first LN ----------------
__global__ void k_embed_ln(const int* __restrict__ x, const float* __restrict__ emb,
                           const float* __restrict__ pos,
                           const float* __restrict__ w, const float* __restrict__ b)
{
    const int row = blockIdx.x;
    const int t   = row & (Tq - 1);
    const int tok = x[row];
    const int c   = threadIdx.x;
    const float4 e = ((const float4*)(emb + (size_t)tok * Dq))[c];
    const float4 p = ((const float4*)(pos + (size_t)t * Dq))[c];
    const float4 v = make_float4(e.x + p.x, e.y + p.y, e.z + p.z, e.w + p.w);
    ((float4*)(g_h + (size_t)row * Dq))[c] = v;
    ln_row(v, w, b, g_lnh + (size_t)row * Dq, c);
}

// ---------------- layernorm: fp32 in -> fp16 out ----------------
__global__ void k_ln(const float* __restrict__ in, __half* __restrict__ out,
                     const float* __restrict__ w, const float* __restrict__ b)
{
    const int row = blockIdx.x;
    const int c = threadIdx.x;
    const float4 v = ((const float4*)(in + (size_t)row * Dq))[c];
    ln_row(v, w, b, out + (size_t)row * Dq, c);
}

// =================== fp16 mma GEMM: C = A[M,K]*B[N,K]^T (half inputs) ===========
// CTA tile MT x 128 (MT = 128 or 64), BK=64, 3-stage cp.async, 256 threads.
// Single barrier per chunk: the post-wait barrier also proves all warps have
// finished reading the stage that issue(kch+2) overwrites.
// MODE 0: C = acc                              (fp32 out)
// MODE 1: fused SwiGLU, interleaved N=2*DFF:   Ch[m][n>>1] = silu(g)*v
// MODE 2: C = C + acc + aux1[n]*aux2h[m,n]     (SSM residual)
// MODE 3: C = C + acc                          (FFN residual)
// MODE 4: C = acc + aux1[n]                    (head bias)
template<int MODE, int MT>
__global__ void __launch_bounds__(256, 2)
k_mma(const __half* __restrict__ A, const __half* __restrict__ Bm,
      float* __restrict__ C, __half* __restrict__ Ch, int M, int N, int K,
      const float* __restrict__ aux1, const __half* __restrict__ aux2)
{
    constexpr int MI   = MT / 32;
    constexpr uint32_t ASTG = (uint32_t)MT * 128;
    constexpr uint32_t BOFF = 3 * ASTG;
    constexpr int WMR  = MT / 2;

    extern __shared__ char smem[];
    const uint32_t sb = (uint32_t)__cvta_generic_to_shared(smem);

    const int tid  = threadIdx.x;
    const int wid  = tid >> 5;
    const int lane = tid & 31;
    const int gid  = lane >> 2;
    const int tig  = lane & 3;
    const int hi   = lane >> 4;
    const int lrow = lane & 15;
    const int rswz = lrow & 7;
    const int wm   = wid & 1;
    const int wn   = wid >> 1;
    const int bm   = blockIdx.x * MT;
    const int bn   = blockIdx.y * 128;

    const int r0  = tid >> 3;
    const int c16 = tid & 7;
    const uint32_t swz16 = (uint32_t)((c16 ^ (r0 & 7)) * 16);
    const __half* Asrc = A  + (size_t)(bm + r0) * K + c16 * 8;
    const __half* Bsrc = Bm + (size_t)(bn + r0) * K + c16 * 8;

    float acc[MI][4][4];
#pragma unroll
    for (int i = 0; i < MI; i++)
#pragma unroll
        for (int j = 0; j < 4; j++)
#pragma unroll
            for (int q = 0; q < 4; q++) acc[i][j][q] = 0.f;

    const int nk = (K + 63) >> 6;

    auto issue = [&](int kc) {
        const uint32_t sta = (uint32_t)(kc % 3) * ASTG;
        const uint32_t stb = BOFF + (uint32_t)(kc % 3) * 16384u;
        const int k0 = kc << 6;
        const int ksz = (k0 + c16 * 8 + 8 <= K) ? 16 : 0;
#pragma unroll
        for (int i = 0; i < MI; i++) {
            const uint32_t dof = (uint32_t)((i * 32 + r0) * 128) + swz16;
            cp16(sb + sta + dof, Asrc + (size_t)(i * 32) * K + k0, ksz);
        }
#pragma unroll
        for (int i = 0; i < 4; i++) {
            const uint32_t dof = (uint32_t)((i * 32 + r0) * 128) + swz16;
            const int bsz = ((bn + i * 32 + r0) < N) ? ksz : 0;
            cp16(sb + stb + dof, Bsrc + (size_t)(i * 32) * K + k0, bsz);
        }
        CP_COMMIT();
    };

    issue(0);
    issue(1);

#pragma unroll 1
    for (int kch = 0; kch < nk; kch++) {
        CP_WAIT1();
        __syncthreads();            // single barrier per chunk (see header comment)
        if (kch + 2 < nk) issue(kch + 2);

        const uint32_t arow = sb + (uint32_t)(kch % 3) * ASTG
                              + (uint32_t)((wm * WMR + lrow) * 128);
        const uint32_t brow = sb + BOFF + (uint32_t)(kch % 3) * 16384u
                              + (uint32_t)((wn * 32 + lrow) * 128);
#pragma unroll
        for (int ks = 0; ks < 4; ks++) {
            const uint32_t csw = (uint32_t)(((ks * 2 + hi) ^ rswz) * 16);
            uint32_t afr[MI][4];
#pragma unroll
            for (int mi = 0; mi < MI; mi++)
                ldm_x4(afr[mi], arow + (uint32_t)(mi * 16 * 128) + csw);
            uint32_t bfr[2][4];
#pragma unroll
            for (int nj = 0; nj < 2; nj++)
                ldm_x4(bfr[nj], brow + (uint32_t)(nj * 16 * 128) + csw);
#pragma unroll
            for (int mi = 0; mi < MI; mi++)
#pragma unroll
                for (int ni = 0; ni < 4; ni++) {
                    const int nj = ni >> 1, h = ni & 1;
                    mma_f16(acc[mi][ni], afr[mi], bfr[nj][h], bfr[nj][h + 2]);
                }
        }
    }
    CP_WAIT0();

    // ---- epilogue ----
#pragma unroll
    for (int mi = 0; mi < MI; mi++) {
        const int r0m = bm + wm * WMR + mi * 16 + gid;
#pragma unroll
        for (int half = 0; half < 2; half++) {
            const int m = r0m + half * 8;
            const size_t rowoff = (size_t)m * N;
#pragma unroll
            for (int ni = 0; ni < 4; ni++) {
                const int n0 = bn + wn * 32 + ni * 8;
                if (n0 >= N) continue;
                const int n = n0 + tig * 2;
                float2 rv;
                rv.x = acc[mi][ni][half * 2 + 0];
                rv.y = acc[mi][ni][half * 2 + 1];
                if (MODE == 0) {
                    *(float2*)(C + rowoff + n) = rv;
                } else if (MODE == 1) {
                    const int f = n >> 1;
                    float r = rv.y * rv.x / (1.f + __expf(-rv.x));
                    Ch[(size_t)m * DFFq + f] = __float2half_rn(r);
                } else if (MODE == 2) {
                    float2* cp = (float2*)(C + rowoff + n);
                    float2 c  = *cp;
                    float2 dp = *(const float2*)(aux1 + n);
                    float2 u  = __half22float2(*(const __half2*)(aux2 + rowoff + n));
                    rv.x += c.x + dp.x * u.x;
                    rv.y += c.y + dp.y * u.y;
                    *cp = rv;
                } else if (MODE == 3) {
                    float2* cp = (float2*)(C + rowoff + n);
                    float2 c = *cp;
                    rv.x += c.x; rv.y += c.y;
                    *cp = rv;
                } else {
                    float2 bb = *(const float2*)(aux1 + n);
                    rv.x += bb.x; rv.y += bb.y;
                    *(float2*)(C + rowoff + n) = rv;
                }
            }
        }
    }
}

#define SMEM64  73728
#define SMEM128 98304

// ---------------- SSM scan phase 1: local chunk scans + carries ----------------
__global__ void k_scan1(const float* __restrict__ loglam)
{
    const int idx   = blockIdx.x * blockDim.x + threadIdx.x;  // 0..32767
    const int s     = idx & (Sq - 1);
    const int b     = (idx >> 8) & 1;
    const int chunk = idx >> 9;
    const float lam = 1.f / (1.f + expf(-loglam[s]));
    float* p = g_bu + ((size_t)(b * Tq + chunk * CLEN)) * Sq + s;
    float h = 0.f;
    float buf[4];
#pragma unroll
    for (int j = 0; j < 4; j++) buf[j] = p[(size_t)j * Sq];
#pragma unroll
    for (int j0 = 0; j0 < CLEN; j0 += 4) {
        float c0 = buf[0], c1 = buf[1], c2 = buf[2], c3 = buf[3];
        if (j0 + 4 < CLEN) {
#pragma unroll
            for (int j = 0; j < 4; j++) buf[j] = p[(size_t)(j0 + 4 + j) * Sq];
        }
        h = fmaf(lam, h, c0); p[(size_t)(j0 + 0) * Sq] = h;
        h = fmaf(lam, h, c1); p[(size_t)(j0 + 1) * Sq] = h;
        h = fmaf(lam, h, c2); p[(size_t)(j0 + 2) * Sq] = h;
        h = fmaf(lam, h, c3); p[(size_t)(j0 + 3) * Sq] = h;
    }
    g_carry[(size_t)chunk * (Bq * Sq) + b * Sq + s] = h;      // [chunk][b][s]
}

// ---------------- scan phase 2+3 fused: local carry-prefix, fixup, half out ----
__global__ void k_scan23(const float* __restrict__ loglam)
{
    const int idx   = blockIdx.x * blockDim.x + threadIdx.x;
    const int s     = idx & (Sq - 1);
    const int b     = (idx >> 8) & 1;
    const int chunk = idx >> 9;                               // warp-uniform
    const float lam = 1.f / (1.f + expf(-loglam[s]));
    float lp = lam;
#pragma unroll
    for (int i = 0; i < 5; i++) lp *= lp;                     // lam^32
    // incoming state for this chunk: H = sum_{c<chunk} lp^{chunk-1-c} * carry[c]
    const float* cb = g_carry + b * Sq + s;
    float H = 0.f;
    for (int c = 0; c < chunk; c++)
        H = fmaf(lp, H, cb[(size_t)c * (Bq * Sq)]);
    const size_t base = ((size_t)(b * Tq + chunk * CLEN)) * Sq + s;
    const float* p = g_bu + base;
    __half* ph = g_buh + base;
    float f = lam;
#pragma unroll
    for (int j0 = 0; j0 < CLEN; j0 += 8) {
        float v[8];
#pragma unroll
        for (int u = 0; u < 8; u++) v[u] = p[(size_t)(j0 + u) * Sq];
#pragma unroll
        for (int u = 0; u < 8; u++) { v[u] += f * H; f *= lam; }
#pragma unroll
        for (int u = 0; u < 8; u++) ph[(size_t)(j0 + u) * Sq] = __float2half_rn(v[u]);
    }
}

// ---------------- orchestration ----------------
extern "C" void kernel_launch(void* const* d_in, const int* in_sizes, int n_in,
                              void* d_out, int out_size)
{
    const int*   x      = (const int*)  d_in[0];
    const float* emb    = (const float*)d_in[1];
    const float* pos    = (const float*)d_in[2];
    const float* loglam = (const float*)d_in[3];
    const float* Bw     = (const float*)d_in[4];
    const float* Cw     = (const float*)d_in[5];
    const float* Dp     = (const float*)d_in[6];
    const float* n1w    = (const float*)d_in[7];
    const float* n1b    = (const float*)d_in[8];
    const float* n2w    = (const float*)d_in[9];
    const float* n2b    = (const float*)d_in[10];
    const float* w1     = (const float*)d_in[11];
    const float* w2     = (const float*)d_in[12];
    const float* w3     = (const float*)d_in[13];
    const float* now    = (const float*)d_in[14];
    const float* nob    = (const float*)d_in[15];
    const float* headW  = (const float*)d_in[16];
    const float* headb  = (const float*)d_in[17];
    float* out = (float*)d_out;

    void *ph, *pb, *plh, *pbh, *pfh, *pw;
    cudaGetSymbolAddress(&ph,  g_h);
    cudaGetSymbolAddress(&pb,  g_bu);
    cudaGetSymbolAddress(&plh, g_lnh);
    cudaGetSymbolAddress(&pbh, g_buh);
    cudaGetSymbolAddress(&pfh, g_ffh);
    cudaGetSymbolAddress(&pw,  g_w);
    float*  h   = (float*)ph;
    float*  bu  = (float*)pb;
    __half* lnh = (__half*)plh;
    __half* buh = (__half*)pbh;
    __half* ffh = (__half*)pfh;
    __half* gw  = (__half*)pw;

    cudaFuncSetAttribute(k_mma<0,64>,  cudaFuncAttributeMaxDynamicSharedMemorySize, SMEM64);
    cudaFuncSetAttribute(k_mma<2,64>,  cudaFuncAttributeMaxDynamicSharedMemorySize, SMEM64);
    cudaFuncSetAttribute(k_mma<3,64>,  cudaFuncAttributeMaxDynamicSharedMemorySize, SMEM64);
    cudaFuncSetAttribute(k_mma<1,128>, cudaFuncAttributeMaxDynamicSharedMemorySize, SMEM128);
    cudaFuncSetAttribute(k_mma<4,128>, cudaFuncAttributeMaxDynamicSharedMemorySize, SMEM128);

    // ---- weight conversion (once per launch) ----
    k_cvt <<<8000, 256>>>(headW, gw + OFF_HEAD, CNT_HEAD / 8);
    k_cvt <<<256,  256>>>(Bw,    gw + OFF_BW,   CNT_BW / 8);
    k_cvt <<<256,  256>>>(Cw,    gw + OFF_CW,   CNT_BW / 8);
    k_cvt2<<<1368, 256>>>(w1, w2, gw + OFF_W12, CNT_W / 8);
    k_cvt <<<1368, 256>>>(w3,    gw + OFF_W3,   CNT_W / 8);

    const dim3 gBu(BT / 64, Sq / 128);                    // 64 x 2
    const dim3 gC (BT / 64, Dq / 128);                    // 64 x 4
    const dim3 gW12(BT / 128, (2 * DFFq + 127) / 128);    // 32 x 22
    const dim3 gW3(BT / 64, Dq / 128);                    // 64 x 4
    const dim3 gHd(BT / 128, Vq / 128);                   // 32 x 250

    // fused embedding + layer-0 first LN
    k_embed_ln<<<BT, 128>>>(x, emb, pos, n1w, n1b);

    const int lBw = Sq * Dq;
    for (int l = 0; l < Lq; l++) {
        // ---- SSM block ----
        if (l > 0) k_ln<<<BT, 128>>>(h, lnh, n1w + l * Dq, n1b + l * Dq);
        k_mma<0,64><<<gBu, 256, SMEM64>>>(lnh, gw + OFF_BW + (size_t)l * lBw,
                                          bu, nullptr, BT, Sq, Dq, nullptr, nullptr);
        k_scan1 <<<128, 256>>>(loglam + l * Sq);
        k_scan23<<<128, 256>>>(loglam + l * Sq);
        k_mma<2,64><<<gC, 256, SMEM64>>>(buh, gw + OFF_CW + (size_t)l * lBw,
                                         h, nullptr, BT, Dq, Sq, Dp + l * Dq, lnh);
        // ---- SwiGLU block (fused w1+w2 interleaved) ----
        k_ln<<<BT, 128>>>(h, lnh, n2w + l * Dq, n2b + l * Dq);
        k_mma<1,128><<<gW12, 256, SMEM128>>>(lnh, gw + OFF_W12 + (size_t)l * 2 * DFFq * Dq,
                                             nullptr, ffh, BT, 2 * DFFq, Dq, nullptr, nullptr);
        k_mma<3,64><<<gW3, 256, SMEM64>>>(ffh, gw + OFF_W3 + (size_t)l * DFFq * Dq,
                                          h, nullptr, BT, Dq, DFFq, nullptr, nullptr);
    }

    // ---- head ----
    k_ln<<<BT, 128>>>(h, lnh, now, nob);
    k_mma<4,128><<<gHd, 256, SMEM128>>>(lnh, gw + OFF_HEAD,
                                        out, nullptr, BT, Vq, Dq, headb, nullptr);
}